// round 1
// baseline (speedup 1.0000x reference)
#include <cuda_runtime.h>
#include <cuda_bf16.h>
#include <math.h>

// Problem constants
#define BB   2
#define LL   1024
#define VV   32000
#define EE   1024
#define HH   16
#define DD   64
#define HID  1024
#define MTOK (BB*LL)      // 2048 tokens

// -------- scratch (static device globals; no allocation) ----------
__device__ float g_emb [MTOK * EE];          // 8 MB
__device__ float g_W3  [EE * 3 * HID];       // 12 MB packed [e][3*1024]
__device__ float g_b3  [3 * HID];
__device__ float g_abw [MTOK * 3 * HID];     // 24 MB  a|b|wout per token
__device__ float g_hs  [MTOK * HID];         // 8 MB   [L,B,HID]
__device__ float g_z   [MTOK * HID];         // 8 MB
__device__ float g_u   [MTOK * HID];         // 8 MB
__device__ float g_mid [MTOK * 4 * HID];     // 32 MB
__device__ float g_hout[MTOK * HID];         // 8 MB
__device__ float g_p   [MTOK * HID];         // 8 MB

// ---------------- pack Wa/Wb/Wo -> W3[e][j], bias3 --------------------------
// Wa[h,e,d] (h*E*D + e*D + d)  ->  W3[e*3072 + h*64+d]
__global__ void pack_w3(const float* __restrict__ Wa, const float* __restrict__ Wb,
                        const float* __restrict__ Wo, const float* __restrict__ ba,
                        const float* __restrict__ bb, const float* __restrict__ bo)
{
    int i = blockIdx.x * blockDim.x + threadIdx.x;   // over E*HID = 1M
    int e = i >> 10, j = i & 1023;
    int h = j >> 6, d = j & 63;
    int src = h * (EE * DD) + e * DD + d;
    g_W3[(size_t)e * 3072 + j]        = Wa[src];
    g_W3[(size_t)e * 3072 + 1024 + j] = Wb[src];
    g_W3[(size_t)e * 3072 + 2048 + j] = Wo[src];
    if (e == 0) {
        g_b3[j]        = ba[j];
        g_b3[1024 + j] = bb[j];
        g_b3[2048 + j] = bo[j];
    }
}

// ---------------- embedding gather ------------------------------------------
__global__ void gather_emb(const int* __restrict__ x, const float* __restrict__ embed)
{
    int i = blockIdx.x * blockDim.x + threadIdx.x;   // over MTOK*256 float4s
    int t = i >> 8, c4 = i & 255;
    int tok = x[t];
    reinterpret_cast<float4*>(g_emb)[i] =
        reinterpret_cast<const float4*>(embed + (size_t)tok * EE)[c4];
}

// ---------------- generic SGEMM 128x128x8, 256 thr, 8x8/thread --------------
// C[M,N] = act(A[M,K] @ B[K,N] + bias[N]) (+ res[M,N])
// act: 0 none, 1 tanh for col<1024, 2 exact gelu
__global__ void __launch_bounds__(256)
sgemm128(const float* __restrict__ A, const float* __restrict__ B,
         const float* __restrict__ bias, const float* __restrict__ res,
         float* __restrict__ C, int M, int N, int K, int act)
{
    __shared__ float As[8][128];
    __shared__ float Bs[8][128];
    int tid = threadIdx.x;
    int bx = blockIdx.x, by = blockIdx.y;

    const float* Ab = A + (size_t)by * 128 * K;
    const float* Bb = B + (size_t)bx * 128;

    int aRow = tid >> 1,  aCol = (tid & 1) << 2;   // 128 rows x 2 float4
    int bRow = tid >> 5,  bCol = (tid & 31) << 2;  // 8 rows x 32 float4
    int ty   = tid >> 4,  tx   = tid & 15;

    float acc[8][8];
    #pragma unroll
    for (int i = 0; i < 8; i++)
        #pragma unroll
        for (int j = 0; j < 8; j++) acc[i][j] = 0.f;

    for (int k0 = 0; k0 < K; k0 += 8) {
        float4 a4 = *reinterpret_cast<const float4*>(Ab + (size_t)aRow * K + k0 + aCol);
        float4 b4 = *reinterpret_cast<const float4*>(Bb + (size_t)(k0 + bRow) * N + bCol);
        As[aCol + 0][aRow] = a4.x;
        As[aCol + 1][aRow] = a4.y;
        As[aCol + 2][aRow] = a4.z;
        As[aCol + 3][aRow] = a4.w;
        *reinterpret_cast<float4*>(&Bs[bRow][bCol]) = b4;
        __syncthreads();

        #pragma unroll
        for (int k = 0; k < 8; k++) {
            float4 ra0 = *reinterpret_cast<const float4*>(&As[k][ty * 8]);
            float4 ra1 = *reinterpret_cast<const float4*>(&As[k][ty * 8 + 4]);
            float4 rb0 = *reinterpret_cast<const float4*>(&Bs[k][tx * 8]);
            float4 rb1 = *reinterpret_cast<const float4*>(&Bs[k][tx * 8 + 4]);
            float ra[8] = {ra0.x, ra0.y, ra0.z, ra0.w, ra1.x, ra1.y, ra1.z, ra1.w};
            float rb[8] = {rb0.x, rb0.y, rb0.z, rb0.w, rb1.x, rb1.y, rb1.z, rb1.w};
            #pragma unroll
            for (int i = 0; i < 8; i++)
                #pragma unroll
                for (int j = 0; j < 8; j++)
                    acc[i][j] = fmaf(ra[i], rb[j], acc[i][j]);
        }
        __syncthreads();
    }

    #pragma unroll
    for (int i = 0; i < 8; i++) {
        int row = by * 128 + ty * 8 + i;
        #pragma unroll
        for (int j = 0; j < 8; j++) {
            int col = bx * 128 + tx * 8 + j;
            float v = acc[i][j] + bias[col];
            if (act == 1) { if (col < 1024) v = tanhf(v); }
            else if (act == 2) { v = 0.5f * v * (1.f + erff(v * 0.70710678118654752f)); }
            if (res) v += res[(size_t)row * N + col];
            C[(size_t)row * N + col] = v;
        }
    }
}

// ---------------- sequential recurrence h = a*h + b*b -----------------------
// one thread per (b, h, d); abw fits in L2 (25 MB) from the preceding GEMM.
__global__ void recurrence()
{
    int j = blockIdx.x * blockDim.x + threadIdx.x;   // 0..2047
    int b = j >> 10, jj = j & 1023;
    const float* base = g_abw + (size_t)b * LL * 3072 + jj;
    float* hsp = g_hs + b * HID + jj;                // [l*2048 + b*1024 + jj]
    float h = 0.f;
    #pragma unroll 8
    for (int l = 0; l < LL; l++) {
        float a  = base[(size_t)l * 3072];
        float bv = base[(size_t)l * 3072 + 1024];
        h = fmaf(a, h, bv * bv);
        hsp[(size_t)l * (BB * HID)] = h;
    }
}

// ---------------- per-head C projection + gating -----------------------------
// z[t, h*64+d] = (sum_d' hs[l,b,h,d'] * Cw[h,d',d] + Cb[h,d]) * wout[t,h*64+d]
__global__ void __launch_bounds__(256)
headmm(const float* __restrict__ Cw, const float* __restrict__ Cb)
{
    __shared__ float S [64][65];   // [token_row][d']
    __shared__ float Cs[64][65];   // [d'][d]
    int tile = blockIdx.x, h = blockIdx.y;
    int t0 = tile * 64;
    int b = t0 >> 10, l0 = t0 & 1023;
    int tid = threadIdx.x;

    for (int i = tid; i < 64 * 64; i += 256) {
        int r = i >> 6, c = i & 63;
        S [r][c] = g_hs[(size_t)(l0 + r) * (BB * HID) + b * HID + h * 64 + c];
        Cs[r][c] = Cw[(size_t)h * 4096 + i];
    }
    __syncthreads();

    int ty = tid >> 4, tx = tid & 15;
    float acc[4][4] = {};
    for (int k = 0; k < 64; k++) {
        float ra[4], rb[4];
        #pragma unroll
        for (int i = 0; i < 4; i++) ra[i] = S[ty * 4 + i][k];
        #pragma unroll
        for (int j = 0; j < 4; j++) rb[j] = Cs[k][tx * 4 + j];
        #pragma unroll
        for (int i = 0; i < 4; i++)
            #pragma unroll
            for (int j = 0; j < 4; j++)
                acc[i][j] = fmaf(ra[i], rb[j], acc[i][j]);
    }

    #pragma unroll
    for (int i = 0; i < 4; i++) {
        int t = t0 + ty * 4 + i;
        #pragma unroll
        for (int j = 0; j < 4; j++) {
            int col = h * 64 + tx * 4 + j;
            float v = acc[i][j] + Cb[col];
            v *= g_abw[(size_t)t * 3072 + 2048 + col];
            g_z[(size_t)t * HID + col] = v;
        }
    }
}

// ---------------- LayerNorm + residual:  u = z + LN(z) ----------------------
__device__ __forceinline__ float warpsum(float v)
{
    #pragma unroll
    for (int o = 16; o; o >>= 1) v += __shfl_xor_sync(0xffffffffu, v, o);
    return v;
}

__global__ void __launch_bounds__(256)
ln_resid(const float* __restrict__ gamma, const float* __restrict__ beta)
{
    int t = blockIdx.x;
    int tid = threadIdx.x;
    const float* z = g_z + (size_t)t * HID;
    float xv[4];
    float s = 0.f, s2 = 0.f;
    #pragma unroll
    for (int k = 0; k < 4; k++) {
        float v = z[tid + 256 * k];
        xv[k] = v; s += v; s2 += v * v;
    }
    __shared__ float sh[2][8];
    s = warpsum(s); s2 = warpsum(s2);
    int w = tid >> 5, ln = tid & 31;
    if (!ln) { sh[0][w] = s; sh[1][w] = s2; }
    __syncthreads();
    if (tid < 32) {
        float a  = (ln < 8) ? sh[0][ln] : 0.f;
        float b2 = (ln < 8) ? sh[1][ln] : 0.f;
        a = warpsum(a); b2 = warpsum(b2);
        if (!ln) { sh[0][0] = a; sh[1][0] = b2; }
    }
    __syncthreads();
    float mu   = sh[0][0] * (1.f / 1024.f);
    float var  = sh[1][0] * (1.f / 1024.f) - mu * mu;
    float rstd = rsqrtf(var + 1e-5f);
    float* u = g_u + (size_t)t * HID;
    #pragma unroll
    for (int k = 0; k < 4; k++) {
        int c = tid + 256 * k;
        float v = xv[k];
        u[c] = v + (v - mu) * rstd * gamma[c] + beta[c];
    }
}

// ---------------- launch ----------------------------------------------------
extern "C" void kernel_launch(void* const* d_in, const int* in_sizes, int n_in,
                              void* d_out, int out_size)
{
    const int*   x      = (const int*)  d_in[0];
    const float* embed  = (const float*)d_in[1];
    const float* Wa     = (const float*)d_in[2];
    const float* ba     = (const float*)d_in[3];
    const float* Wb     = (const float*)d_in[4];
    const float* bb     = (const float*)d_in[5];
    const float* Wo     = (const float*)d_in[6];
    const float* bo     = (const float*)d_in[7];
    const float* Cw     = (const float*)d_in[8];
    const float* Cb     = (const float*)d_in[9];
    const float* proj_w = (const float*)d_in[10];
    const float* proj_b = (const float*)d_in[11];
    const float* gamma  = (const float*)d_in[12];
    const float* beta   = (const float*)d_in[13];
    const float* ffn1_w = (const float*)d_in[14];
    const float* ffn1_b = (const float*)d_in[15];
    const float* ffn2_w = (const float*)d_in[16];
    const float* ffn2_b = (const float*)d_in[17];
    const float* out_w  = (const float*)d_in[18];
    const float* out_b  = (const float*)d_in[19];
    float* out = (float*)d_out;

    float *emb, *W3, *b3, *abw, *hs, *z, *u, *mid, *hout, *p;
    cudaGetSymbolAddress((void**)&emb,  g_emb);
    cudaGetSymbolAddress((void**)&W3,   g_W3);
    cudaGetSymbolAddress((void**)&b3,   g_b3);
    cudaGetSymbolAddress((void**)&abw,  g_abw);
    cudaGetSymbolAddress((void**)&hs,   g_hs);
    cudaGetSymbolAddress((void**)&z,    g_z);
    cudaGetSymbolAddress((void**)&u,    g_u);
    cudaGetSymbolAddress((void**)&mid,  g_mid);
    cudaGetSymbolAddress((void**)&hout, g_hout);
    cudaGetSymbolAddress((void**)&p,    g_p);
    (void)in_sizes; (void)n_in; (void)out_size;
    (void)hs; (void)z;  // used via device globals inside kernels

    // 1. pack projection weights
    pack_w3<<<(EE * HID) / 256, 256>>>(Wa, Wb, Wo, ba, bb, bo);
    // 2. embedding gather
    gather_emb<<<(MTOK * 256) / 256, 256>>>(x, embed);
    // 3. packed projections: abw = [tanh(emb@Wa'+ba) | emb@Wb'+bb | emb@Wo'+bo]
    sgemm128<<<dim3(3072 / 128, MTOK / 128), 256>>>(emb, W3, b3, nullptr, abw,
                                                    MTOK, 3072, EE, 1);
    // 4. recurrence
    recurrence<<<8, 256>>>();
    // 5. per-head C projection + gating
    headmm<<<dim3(MTOK / 64, HH), 256>>>(Cw, Cb);
    // 6. u = z + LN(z)
    ln_resid<<<MTOK, 256>>>(gamma, beta);
    // 7. FFN1 + exact gelu
    sgemm128<<<dim3(4096 / 128, MTOK / 128), 256>>>(u, ffn1_w, ffn1_b, nullptr, mid,
                                                    MTOK, 4096, HID, 2);
    // 8. FFN2 + residual u
    sgemm128<<<dim3(1024 / 128, MTOK / 128), 256>>>(mid, ffn2_w, ffn2_b, u, hout,
                                                    MTOK, 1024, 4096, 0);
    // 9. proj
    sgemm128<<<dim3(1024 / 128, MTOK / 128), 256>>>(hout, proj_w, proj_b, nullptr, p,
                                                    MTOK, 1024, HID, 0);
    // 10. logits
    sgemm128<<<dim3(VV / 128, MTOK / 128), 256>>>(p, out_w, out_b, nullptr, out,
                                                  MTOK, VV, HID, 0);
}

// round 3
// speedup vs baseline: 1.0948x; 1.0948x over previous
#include <cuda_runtime.h>
#include <cuda_bf16.h>
#include <mma.h>
#include <math.h>

using namespace nvcuda;

// Problem constants
#define BB   2
#define LL   1024
#define VV   32000
#define EE   1024
#define HH   16
#define DD   64
#define HID  1024
#define MTOK (BB*LL)      // 2048 tokens

// -------- scratch (static device globals; no allocation) ----------
__device__ float g_emb  [MTOK * EE];          // 8 MB
__device__ float g_W3   [EE * 3 * HID];       // 12 MB packed [e][3*1024]
__device__ float g_b3   [3 * HID];
__device__ float g_abw  [MTOK * 3 * HID];     // 24 MB  a|b|wout per token
__device__ float g_hs   [MTOK * HID];         // 8 MB   [L,B,HID]
__device__ float g_z    [MTOK * HID];         // 8 MB
__device__ float g_u    [MTOK * HID];         // 8 MB
__device__ float g_mid  [MTOK * 4 * HID];     // 32 MB
__device__ float g_hout [MTOK * HID];         // 8 MB
__device__ float g_p    [MTOK * HID];         // 8 MB
__device__ float g_scanA[32 * MTOK];          // chunk summaries
__device__ float g_scanC[32 * MTOK];
__device__ float g_hst  [32 * MTOK];          // chunk start states

// ---------------- pack Wa/Wb/Wo -> W3[e][j], bias3 --------------------------
__global__ void pack_w3(const float* __restrict__ Wa, const float* __restrict__ Wb,
                        const float* __restrict__ Wo, const float* __restrict__ ba,
                        const float* __restrict__ bb, const float* __restrict__ bo)
{
    int i = blockIdx.x * blockDim.x + threadIdx.x;   // over E*HID = 1M
    int e = i >> 10, j = i & 1023;
    int h = j >> 6, d = j & 63;
    int src = h * (EE * DD) + e * DD + d;
    g_W3[(size_t)e * 3072 + j]        = Wa[src];
    g_W3[(size_t)e * 3072 + 1024 + j] = Wb[src];
    g_W3[(size_t)e * 3072 + 2048 + j] = Wo[src];
    if (e == 0) {
        g_b3[j]        = ba[j];
        g_b3[1024 + j] = bb[j];
        g_b3[2048 + j] = bo[j];
    }
}

// ---------------- embedding gather ------------------------------------------
__global__ void gather_emb(const int* __restrict__ x, const float* __restrict__ embed)
{
    int i = blockIdx.x * blockDim.x + threadIdx.x;   // over MTOK*256 float4s
    int t = i >> 8, c4 = i & 255;
    int tok = x[t];
    reinterpret_cast<float4*>(g_emb)[i] =
        reinterpret_cast<const float4*>(embed + (size_t)tok * EE)[c4];
}

// ---------------- generic SGEMM 128x128x8, 256 thr, 8x8/thread --------------
// C[M,N] = act(A[M,K] @ B[K,N] + bias[N]) (+ res[M,N])
// act: 0 none, 1 tanh for col<1024, 2 exact gelu
__global__ void __launch_bounds__(256)
sgemm128(const float* __restrict__ A, const float* __restrict__ B,
         const float* __restrict__ bias, const float* __restrict__ res,
         float* __restrict__ C, int M, int N, int K, int act)
{
    __shared__ float As[8][128];
    __shared__ float Bs[8][128];
    int tid = threadIdx.x;
    int bx = blockIdx.x, by = blockIdx.y;

    const float* Ab = A + (size_t)by * 128 * K;
    const float* Bb = B + (size_t)bx * 128;

    int aRow = tid >> 1,  aCol = (tid & 1) << 2;
    int bRow = tid >> 5,  bCol = (tid & 31) << 2;
    int ty   = tid >> 4,  tx   = tid & 15;

    float acc[8][8];
    #pragma unroll
    for (int i = 0; i < 8; i++)
        #pragma unroll
        for (int j = 0; j < 8; j++) acc[i][j] = 0.f;

    for (int k0 = 0; k0 < K; k0 += 8) {
        float4 a4 = *reinterpret_cast<const float4*>(Ab + (size_t)aRow * K + k0 + aCol);
        float4 b4 = *reinterpret_cast<const float4*>(Bb + (size_t)(k0 + bRow) * N + bCol);
        As[aCol + 0][aRow] = a4.x;
        As[aCol + 1][aRow] = a4.y;
        As[aCol + 2][aRow] = a4.z;
        As[aCol + 3][aRow] = a4.w;
        *reinterpret_cast<float4*>(&Bs[bRow][bCol]) = b4;
        __syncthreads();

        #pragma unroll
        for (int k = 0; k < 8; k++) {
            float4 ra0 = *reinterpret_cast<const float4*>(&As[k][ty * 8]);
            float4 ra1 = *reinterpret_cast<const float4*>(&As[k][ty * 8 + 4]);
            float4 rb0 = *reinterpret_cast<const float4*>(&Bs[k][tx * 8]);
            float4 rb1 = *reinterpret_cast<const float4*>(&Bs[k][tx * 8 + 4]);
            float ra[8] = {ra0.x, ra0.y, ra0.z, ra0.w, ra1.x, ra1.y, ra1.z, ra1.w};
            float rb[8] = {rb0.x, rb0.y, rb0.z, rb0.w, rb1.x, rb1.y, rb1.z, rb1.w};
            #pragma unroll
            for (int i = 0; i < 8; i++)
                #pragma unroll
                for (int j = 0; j < 8; j++)
                    acc[i][j] = fmaf(ra[i], rb[j], acc[i][j]);
        }
        __syncthreads();
    }

    #pragma unroll
    for (int i = 0; i < 8; i++) {
        int row = by * 128 + ty * 8 + i;
        #pragma unroll
        for (int j = 0; j < 8; j++) {
            int col = bx * 128 + tx * 8 + j;
            float v = acc[i][j] + bias[col];
            if (act == 1) { if (col < 1024) v = tanhf(v); }
            else if (act == 2) { v = 0.5f * v * (1.f + erff(v * 0.70710678118654752f)); }
            if (res) v += res[(size_t)row * N + col];
            C[(size_t)row * N + col] = v;
        }
    }
}

// ---------------- recurrence as 3-phase chunked affine scan ------------------
// h_l = a_l * h_{l-1} + b_l^2  is affine; compose over chunks of 32 steps.
__global__ void scan1()
{
    int c = blockIdx.x;                                  // chunk 0..31
    int q = blockIdx.y * 256 + threadIdx.x;              // chain 0..2047
    int b = q >> 10, jj = q & 1023;
    const float* base = g_abw + (size_t)b * LL * 3072 + jj;
    int l0 = c * 32;
    float A = 1.f, C = 0.f;
    #pragma unroll 8
    for (int i = 0; i < 32; i++) {
        float a  = base[(size_t)(l0 + i) * 3072];
        float bv = base[(size_t)(l0 + i) * 3072 + 1024];
        C = fmaf(a, C, bv * bv);
        A *= a;
    }
    g_scanA[c * MTOK + q] = A;
    g_scanC[c * MTOK + q] = C;
}

__global__ void scan2()
{
    int q = blockIdx.x * 256 + threadIdx.x;              // chain 0..2047
    float h = 0.f;
    #pragma unroll
    for (int c = 0; c < 32; c++) {
        g_hst[c * MTOK + q] = h;
        h = fmaf(g_scanA[c * MTOK + q], h, g_scanC[c * MTOK + q]);
    }
}

__global__ void scan3()
{
    int c = blockIdx.x;
    int q = blockIdx.y * 256 + threadIdx.x;
    int b = q >> 10, jj = q & 1023;
    const float* base = g_abw + (size_t)b * LL * 3072 + jj;
    float* hsp = g_hs + b * HID + jj;
    float h = g_hst[c * MTOK + q];
    int l0 = c * 32;
    #pragma unroll 8
    for (int i = 0; i < 32; i++) {
        int l = l0 + i;
        float a  = base[(size_t)l * 3072];
        float bv = base[(size_t)l * 3072 + 1024];
        h = fmaf(a, h, bv * bv);
        hsp[(size_t)l * (BB * HID)] = h;
    }
}

// ---------------- per-head C projection + gating -----------------------------
__global__ void __launch_bounds__(256)
headmm(const float* __restrict__ Cw, const float* __restrict__ Cb)
{
    __shared__ float S [64][65];
    __shared__ float Cs[64][65];
    int tile = blockIdx.x, h = blockIdx.y;
    int t0 = tile * 64;
    int b = t0 >> 10, l0 = t0 & 1023;
    int tid = threadIdx.x;

    for (int i = tid; i < 64 * 64; i += 256) {
        int r = i >> 6, c = i & 63;
        S [r][c] = g_hs[(size_t)(l0 + r) * (BB * HID) + b * HID + h * 64 + c];
        Cs[r][c] = Cw[(size_t)h * 4096 + i];
    }
    __syncthreads();

    int ty = tid >> 4, tx = tid & 15;
    float acc[4][4] = {};
    for (int k = 0; k < 64; k++) {
        float ra[4], rb[4];
        #pragma unroll
        for (int i = 0; i < 4; i++) ra[i] = S[ty * 4 + i][k];
        #pragma unroll
        for (int j = 0; j < 4; j++) rb[j] = Cs[k][tx * 4 + j];
        #pragma unroll
        for (int i = 0; i < 4; i++)
            #pragma unroll
            for (int j = 0; j < 4; j++)
                acc[i][j] = fmaf(ra[i], rb[j], acc[i][j]);
    }

    #pragma unroll
    for (int i = 0; i < 4; i++) {
        int t = t0 + ty * 4 + i;
        #pragma unroll
        for (int j = 0; j < 4; j++) {
            int col = h * 64 + tx * 4 + j;
            float v = acc[i][j] + Cb[col];
            v *= g_abw[(size_t)t * 3072 + 2048 + col];
            g_z[(size_t)t * HID + col] = v;
        }
    }
}

// ---------------- LayerNorm + residual:  u = z + LN(z) ----------------------
__device__ __forceinline__ float warpsum(float v)
{
    #pragma unroll
    for (int o = 16; o; o >>= 1) v += __shfl_xor_sync(0xffffffffu, v, o);
    return v;
}

__global__ void __launch_bounds__(256)
ln_resid(const float* __restrict__ gamma, const float* __restrict__ beta)
{
    int t = blockIdx.x;
    int tid = threadIdx.x;
    const float* z = g_z + (size_t)t * HID;
    float xv[4];
    float s = 0.f, s2 = 0.f;
    #pragma unroll
    for (int k = 0; k < 4; k++) {
        float v = z[tid + 256 * k];
        xv[k] = v; s += v; s2 += v * v;
    }
    __shared__ float sh[2][8];
    s = warpsum(s); s2 = warpsum(s2);
    int w = tid >> 5, ln = tid & 31;
    if (!ln) { sh[0][w] = s; sh[1][w] = s2; }
    __syncthreads();
    if (tid < 32) {
        float a  = (ln < 8) ? sh[0][ln] : 0.f;
        float b2 = (ln < 8) ? sh[1][ln] : 0.f;
        a = warpsum(a); b2 = warpsum(b2);
        if (!ln) { sh[0][0] = a; sh[1][0] = b2; }
    }
    __syncthreads();
    float mu   = sh[0][0] * (1.f / 1024.f);
    float var  = sh[1][0] * (1.f / 1024.f) - mu * mu;
    float rstd = rsqrtf(var + 1e-5f);
    float* u = g_u + (size_t)t * HID;
    #pragma unroll
    for (int k = 0; k < 4; k++) {
        int c = tid + 256 * k;
        float v = xv[k];
        u[c] = v + (v - mu) * rstd * gamma[c] + beta[c];
    }
}

// ---------------- tf32 WMMA GEMM (for the big out_w GEMM) -------------------
// C[M,N] = A[M,K] @ B[K,N] + bias[N], tf32 inputs (RN-converted), fp32 accum.
// Block tile 128x128, 8 warps of 32x64 (2x4 wmma m16n16k8 tiles).
__global__ void __launch_bounds__(256)
wmma_tf32(const float* __restrict__ A, const float* __restrict__ B,
          const float* __restrict__ bias, float* __restrict__ C,
          int M, int N, int K)
{
    __shared__ float As[128][20];
    __shared__ float Bs[16][132];
    __shared__ float cbuf[8][16][20];

    int tid = threadIdx.x, wid = tid >> 5, lane = tid & 31;
    int brow = blockIdx.y * 128, bcol = blockIdx.x * 128;
    int wm = (wid & 3) * 32, wn = (wid >> 2) * 64;

    wmma::fragment<wmma::accumulator, 16, 16, 8, float> acc[2][4];
    #pragma unroll
    for (int i = 0; i < 2; i++)
        #pragma unroll
        for (int j = 0; j < 4; j++)
            wmma::fill_fragment(acc[i][j], 0.f);

    for (int k0 = 0; k0 < K; k0 += 16) {
        #pragma unroll
        for (int r = 0; r < 2; r++) {
            int idx = tid + r * 256;               // 0..511 float4s of A 128x16
            int row = idx >> 2, col = (idx & 3) << 2;
            float4 v = *reinterpret_cast<const float4*>(
                A + (size_t)(brow + row) * K + k0 + col);
            *reinterpret_cast<float4*>(&As[row][col]) = v;
        }
        #pragma unroll
        for (int r = 0; r < 2; r++) {
            int idx = tid + r * 256;               // 0..511 float4s of B 16x128
            int row = idx >> 5, col = (idx & 31) << 2;
            float4 v = *reinterpret_cast<const float4*>(
                B + (size_t)(k0 + row) * N + bcol + col);
            *reinterpret_cast<float4*>(&Bs[row][col]) = v;
        }
        __syncthreads();

        #pragma unroll
        for (int kk = 0; kk < 16; kk += 8) {
            wmma::fragment<wmma::matrix_a, 16, 16, 8, wmma::precision::tf32,
                           wmma::row_major> af[2];
            wmma::fragment<wmma::matrix_b, 16, 16, 8, wmma::precision::tf32,
                           wmma::row_major> bf[4];
            #pragma unroll
            for (int i = 0; i < 2; i++) {
                wmma::load_matrix_sync(af[i], &As[wm + i * 16][kk], 20);
                #pragma unroll
                for (int t = 0; t < af[i].num_elements; t++)
                    af[i].x[t] = wmma::__float_to_tf32(af[i].x[t]);
            }
            #pragma unroll
            for (int j = 0; j < 4; j++) {
                wmma::load_matrix_sync(bf[j], &Bs[kk][wn + j * 16], 132);
                #pragma unroll
                for (int t = 0; t < bf[j].num_elements; t++)
                    bf[j].x[t] = wmma::__float_to_tf32(bf[j].x[t]);
            }
            #pragma unroll
            for (int i = 0; i < 2; i++)
                #pragma unroll
                for (int j = 0; j < 4; j++)
                    wmma::mma_sync(acc[i][j], af[i], bf[j], acc[i][j]);
        }
        __syncthreads();
    }

    // epilogue: stage each 16x16 tile in smem, add bias, coalesced store
    #pragma unroll
    for (int i = 0; i < 2; i++) {
        #pragma unroll
        for (int j = 0; j < 4; j++) {
            wmma::store_matrix_sync(&cbuf[wid][0][0], acc[i][j], 20,
                                    wmma::mem_row_major);
            __syncwarp();
            int row0 = brow + wm + i * 16, col0 = bcol + wn + j * 16;
            #pragma unroll
            for (int e = 0; e < 8; e++) {
                int idx = lane + e * 32;           // 0..255
                int r = idx >> 4, c = idx & 15;
                C[(size_t)(row0 + r) * N + col0 + c] = cbuf[wid][r][c] + bias[col0 + c];
            }
            __syncwarp();
        }
    }
}

// ---------------- launch ----------------------------------------------------
extern "C" void kernel_launch(void* const* d_in, const int* in_sizes, int n_in,
                              void* d_out, int out_size)
{
    const int*   x      = (const int*)  d_in[0];
    const float* embed  = (const float*)d_in[1];
    const float* Wa     = (const float*)d_in[2];
    const float* ba     = (const float*)d_in[3];
    const float* Wb     = (const float*)d_in[4];
    const float* bb     = (const float*)d_in[5];
    const float* Wo     = (const float*)d_in[6];
    const float* bo     = (const float*)d_in[7];
    const float* Cw     = (const float*)d_in[8];
    const float* Cb     = (const float*)d_in[9];
    const float* proj_w = (const float*)d_in[10];
    const float* proj_b = (const float*)d_in[11];
    const float* gamma  = (const float*)d_in[12];
    const float* beta   = (const float*)d_in[13];
    const float* ffn1_w = (const float*)d_in[14];
    const float* ffn1_b = (const float*)d_in[15];
    const float* ffn2_w = (const float*)d_in[16];
    const float* ffn2_b = (const float*)d_in[17];
    const float* out_w  = (const float*)d_in[18];
    const float* out_b  = (const float*)d_in[19];
    float* out = (float*)d_out;

    float *emb, *W3, *b3, *abw, *u, *mid, *hout, *p;
    cudaGetSymbolAddress((void**)&emb,  g_emb);
    cudaGetSymbolAddress((void**)&W3,   g_W3);
    cudaGetSymbolAddress((void**)&b3,   g_b3);
    cudaGetSymbolAddress((void**)&abw,  g_abw);
    cudaGetSymbolAddress((void**)&u,    g_u);
    cudaGetSymbolAddress((void**)&mid,  g_mid);
    cudaGetSymbolAddress((void**)&hout, g_hout);
    cudaGetSymbolAddress((void**)&p,    g_p);
    (void)in_sizes; (void)n_in; (void)out_size;

    // 1. pack projection weights
    pack_w3<<<(EE * HID) / 256, 256>>>(Wa, Wb, Wo, ba, bb, bo);
    // 2. embedding gather
    gather_emb<<<(MTOK * 256) / 256, 256>>>(x, embed);
    // 3. packed projections: abw = [tanh(emb@Wa'+ba) | emb@Wb'+bb | emb@Wo'+bo]
    sgemm128<<<dim3(3072 / 128, MTOK / 128), 256>>>(emb, W3, b3, nullptr, abw,
                                                    MTOK, 3072, EE, 1);
    // 4. recurrence (chunked affine scan)
    scan1<<<dim3(32, 8), 256>>>();
    scan2<<<8, 256>>>();
    scan3<<<dim3(32, 8), 256>>>();
    // 5. per-head C projection + gating
    headmm<<<dim3(MTOK / 64, HH), 256>>>(Cw, Cb);
    // 6. u = z + LN(z)
    ln_resid<<<MTOK, 256>>>(gamma, beta);
    // 7. FFN1 + exact gelu
    sgemm128<<<dim3(4096 / 128, MTOK / 128), 256>>>(u, ffn1_w, ffn1_b, nullptr, mid,
                                                    MTOK, 4096, HID, 2);
    // 8. FFN2 + residual u
    sgemm128<<<dim3(1024 / 128, MTOK / 128), 256>>>(mid, ffn2_w, ffn2_b, u, hout,
                                                    MTOK, 1024, 4096, 0);
    // 9. proj (fp32 — feeds the final GEMM, keep exact)
    sgemm128<<<dim3(1024 / 128, MTOK / 128), 256>>>(hout, proj_w, proj_b, nullptr, p,
                                                    MTOK, 1024, HID, 0);
    // 10. logits via tf32 tensor cores (dominant GEMM: 2048x32000x1024)
    wmma_tf32<<<dim3(VV / 128, MTOK / 128), 256>>>(p, out_w, out_b, out,
                                                   MTOK, VV, HID);
}

// round 9
// speedup vs baseline: 2.9155x; 2.6632x over previous
#include <cuda_runtime.h>
#include <cuda_bf16.h>
#include <math.h>
#include <stdint.h>

// Problem constants
#define BB   2
#define LL   1024
#define VV   32000
#define EE   1024
#define HH   16
#define DD   64
#define HID  1024
#define MTOK (BB*LL)      // 2048 tokens

// ===================== helpers (plain sm_80+ PTX only) ======================
__device__ __forceinline__ uint32_t smem_u32(const void* p) {
    uint32_t a;
    asm("{ .reg .u64 t; cvta.to.shared.u64 t, %1; cvt.u32.u64 %0, t; }"
        : "=r"(a) : "l"(p));
    return a;
}
#define SMEM_SWIZZLE_128B(o) ((o) ^ (((o) >> 3) & 0x70))

#define CP_ASYNC16(dst, src) \
    asm volatile("cp.async.cg.shared.global [%0], [%1], 16;" \
                 :: "r"(dst), "l"(src) : "memory")
#define CP_COMMIT() asm volatile("cp.async.commit_group;" ::: "memory")
#define CP_WAIT1()  asm volatile("cp.async.wait_group 1;" ::: "memory")
#define CP_WAIT0()  asm volatile("cp.async.wait_group 0;" ::: "memory")

#define LDSM_X4(d, addr) \
    asm volatile("ldmatrix.sync.aligned.m8n8.x4.shared.b16 {%0,%1,%2,%3}, [%4];" \
                 : "=r"((d)[0]), "=r"((d)[1]), "=r"((d)[2]), "=r"((d)[3]) : "r"(addr))

#define MMA_BF16(c, a, b0_, b1_) \
    asm volatile("mma.sync.aligned.m16n8k16.row.col.f32.bf16.bf16.f32 " \
                 "{%0,%1,%2,%3}, {%4,%5,%6,%7}, {%8,%9}, {%0,%1,%2,%3};" \
                 : "+f"((c)[0]), "+f"((c)[1]), "+f"((c)[2]), "+f"((c)[3]) \
                 : "r"((a)[0]), "r"((a)[1]), "r"((a)[2]), "r"((a)[3]), \
                   "r"(b0_), "r"(b1_))

// ===================== scratch (device globals; no allocation) ==============
__device__ float g_abw  [MTOK * 3 * HID];
__device__ float g_hs   [MTOK * HID];
__device__ float g_z    [MTOK * HID];
__device__ float g_u    [MTOK * HID];
__device__ float g_b3   [3 * HID];
__device__ float g_scanA[32 * MTOK];
__device__ float g_scanC[32 * MTOK];
__device__ float g_hst  [32 * MTOK];

__device__ __nv_bfloat16 g_embH [MTOK * EE],      g_embL [MTOK * EE];
__device__ __nv_bfloat16 g_uH   [MTOK * HID],     g_uL   [MTOK * HID];
__device__ __nv_bfloat16 g_midH [MTOK * 4 * HID], g_midL [MTOK * 4 * HID];
__device__ __nv_bfloat16 g_houtH[MTOK * HID],     g_houtL[MTOK * HID];
__device__ __nv_bfloat16 g_pH   [MTOK * HID],     g_pL   [MTOK * HID];
__device__ __nv_bfloat16 g_W3tH [3 * HID * EE],   g_W3tL [3 * HID * EE];
__device__ __nv_bfloat16 g_f1tH [4 * HID * HID],  g_f1tL [4 * HID * HID];
__device__ __nv_bfloat16 g_f2tH [4 * HID * HID],  g_f2tL [4 * HID * HID];
__device__ __nv_bfloat16 g_pjtH [HID * HID],      g_pjtL [HID * HID];
__device__ __nv_bfloat16 g_owtH [(size_t)VV * HID], g_owtL[(size_t)VV * HID];

// ============= transpose + bf16 split: in[K,N] f32 -> out[N,K] hi/lo ========
__global__ void tsplit(const float* __restrict__ in, __nv_bfloat16* __restrict__ oh,
                       __nv_bfloat16* __restrict__ ol, int K, int N,
                       long inZ, long outZrow)
{
    __shared__ float s[32][33];
    int k0 = blockIdx.x * 32, n0 = blockIdx.y * 32, z = blockIdx.z;
    in += (size_t)z * inZ;
    size_t rbase = (size_t)z * outZrow + n0;
    int tx = threadIdx.x, ty = threadIdx.y;
    #pragma unroll
    for (int i = 0; i < 4; i++)
        s[ty + 8 * i][tx] = in[(size_t)(k0 + ty + 8 * i) * N + n0 + tx];
    __syncthreads();
    #pragma unroll
    for (int i = 0; i < 4; i++) {
        float v = s[tx][ty + 8 * i];
        size_t o = (rbase + ty + 8 * i) * (size_t)K + k0 + tx;
        __nv_bfloat16 h = __float2bfloat16(v);
        oh[o] = h;
        ol[o] = __float2bfloat16(v - __bfloat162float(h));
    }
}

__global__ void pack_b3k(const float* __restrict__ ba, const float* __restrict__ bb,
                         const float* __restrict__ bo)
{
    int j = blockIdx.x * 256 + threadIdx.x;
    g_b3[j] = ba[j]; g_b3[1024 + j] = bb[j]; g_b3[2048 + j] = bo[j];
}

// ============= embedding gather + bf16 split ================================
__global__ void gather_emb(const int* __restrict__ x, const float* __restrict__ embed)
{
    int i = blockIdx.x * blockDim.x + threadIdx.x;   // over MTOK*256 float4s
    int t = i >> 8, c4 = i & 255;
    int tok = x[t];
    float4 v = reinterpret_cast<const float4*>(embed + (size_t)tok * EE)[c4];
    size_t o = (size_t)t * EE + c4 * 4;
    float vv[4] = {v.x, v.y, v.z, v.w};
    #pragma unroll
    for (int j = 0; j < 4; j++) {
        __nv_bfloat16 h = __float2bfloat16(vv[j]);
        g_embH[o + j] = h;
        g_embL[o + j] = __float2bfloat16(vv[j] - __bfloat162float(h));
    }
}

// ===================== split-bf16 HMMA GEMM =================================
// D[M,N] = Ahi@Bhi^T + Ahi@Blo^T + Alo@Bhi^T  (fp32 accum in registers)
// A*[M,K] bf16 row-major; B*[N,K] bf16 row-major (weight pre-transposed).
// Epilogue: +bias, act(0 none,1 tanh col<1024,2 gelu), +res(fp32), writes
// outF (fp32) and/or outHi/outLo (bf16 split), all [M,N] row-major.
//
// Block 128x128, K-chunk 64, double-buffered cp.async (2 x 64KB stages).
// 8 warps, each 64(M) x 32(N): wm=(wid&1)*64, wn=(wid>>1)*32.
#define STAGE_BYTES 65536
#define GSMEM (2 * STAGE_BYTES)

__device__ __forceinline__ void load_chunk(
    uint32_t sdst, const __nv_bfloat16* __restrict__ Ahi,
    const __nv_bfloat16* __restrict__ Alo, const __nv_bfloat16* __restrict__ Bhi,
    const __nv_bfloat16* __restrict__ Blo, int m0, int n0, int K, int k0, int tid)
{
    #pragma unroll
    for (int t = 0; t < 4; t++) {
        int idx = tid + t * 256;               // 0..1023 16B lines per tile
        int r = idx >> 3, c8 = idx & 7;
        uint32_t off = SMEM_SWIZZLE_128B(r * 128 + c8 * 16);
        CP_ASYNC16(sdst + off,                 Ahi + (size_t)(m0 + r) * K + k0 + c8 * 8);
        CP_ASYNC16(sdst + 16384 + off,         Alo + (size_t)(m0 + r) * K + k0 + c8 * 8);
        CP_ASYNC16(sdst + 32768 + off,         Bhi + (size_t)(n0 + r) * K + k0 + c8 * 8);
        CP_ASYNC16(sdst + 49152 + off,         Blo + (size_t)(n0 + r) * K + k0 + c8 * 8);
    }
}

__global__ void __launch_bounds__(256)
gemm_tc(const __nv_bfloat16* __restrict__ Ahi, const __nv_bfloat16* __restrict__ Alo,
        const __nv_bfloat16* __restrict__ Bhi, const __nv_bfloat16* __restrict__ Blo,
        const float* __restrict__ bias, const float* __restrict__ res,
        float* __restrict__ outF, __nv_bfloat16* __restrict__ outHi,
        __nv_bfloat16* __restrict__ outLo, int N, int K, int act)
{
    extern __shared__ char smem[];
    const int tid = threadIdx.x;
    const int wid = tid >> 5, lane = tid & 31;
    const int m0 = blockIdx.x * 128, n0 = blockIdx.y * 128;
    const int wm = (wid & 1) * 64, wn = (wid >> 1) * 32;
    const uint32_t sb = smem_u32(smem);

    float acc[4][4][4];
    #pragma unroll
    for (int mi = 0; mi < 4; mi++)
        #pragma unroll
        for (int ni = 0; ni < 4; ni++)
            #pragma unroll
            for (int e = 0; e < 4; e++) acc[mi][ni][e] = 0.f;

    const int nch = K / 64;
    load_chunk(sb, Ahi, Alo, Bhi, Blo, m0, n0, K, 0, tid);
    CP_COMMIT();

    for (int it = 0; it < nch; it++) {
        if (it + 1 < nch) {
            load_chunk(sb + ((it + 1) & 1) * STAGE_BYTES,
                       Ahi, Alo, Bhi, Blo, m0, n0, K, (it + 1) * 64, tid);
            CP_COMMIT();
            CP_WAIT1();
        } else {
            CP_WAIT0();
        }
        __syncthreads();

        const uint32_t st = sb + (it & 1) * STAGE_BYTES;
        const uint32_t tA1 = st, tA2 = st + 16384, tB1 = st + 32768, tB2 = st + 49152;
        const int lr = lane & 15, lg = (lane >> 4) << 4;

        #pragma unroll
        for (int kk = 0; kk < 4; kk++) {
            uint32_t a1[4][4], a2[4][4], b1[2][4], b2[2][4];
            #pragma unroll
            for (int mi = 0; mi < 4; mi++) {
                uint32_t off = SMEM_SWIZZLE_128B((wm + mi * 16 + lr) * 128 + kk * 32 + lg);
                LDSM_X4(a1[mi], tA1 + off);
                LDSM_X4(a2[mi], tA2 + off);
            }
            #pragma unroll
            for (int pi = 0; pi < 2; pi++) {
                uint32_t off = SMEM_SWIZZLE_128B((wn + pi * 16 + lr) * 128 + kk * 32 + lg);
                LDSM_X4(b1[pi], tB1 + off);
                LDSM_X4(b2[pi], tB2 + off);
            }
            // ldmatrix.x4 mats: 0=n0-7/k0-7, 1=n8-15/k0-7, 2=n0-7/k8-15, 3=n8-15/k8-15
            // B operand for n-tile 2pi   = {b[pi][0], b[pi][2]}
            //               n-tile 2pi+1 = {b[pi][1], b[pi][3]}
            #pragma unroll
            for (int mi = 0; mi < 4; mi++) {
                #pragma unroll
                for (int pi = 0; pi < 2; pi++) {
                    MMA_BF16(acc[mi][2 * pi],     a1[mi], b1[pi][0], b1[pi][2]);
                    MMA_BF16(acc[mi][2 * pi + 1], a1[mi], b1[pi][1], b1[pi][3]);
                    MMA_BF16(acc[mi][2 * pi],     a1[mi], b2[pi][0], b2[pi][2]);
                    MMA_BF16(acc[mi][2 * pi + 1], a1[mi], b2[pi][1], b2[pi][3]);
                    MMA_BF16(acc[mi][2 * pi],     a2[mi], b1[pi][0], b1[pi][2]);
                    MMA_BF16(acc[mi][2 * pi + 1], a2[mi], b1[pi][1], b1[pi][3]);
                }
            }
        }
        __syncthreads();
    }

    // ---- epilogue: 4 passes of 32 columns via padded SMEM restage ----
    float* ep = reinterpret_cast<float*>(smem);    // [128][36], reuses stage 0
    for (int p = 0; p < 4; p++) {
        if ((wid >> 1) == p) {                     // warps 2p, 2p+1 own these cols
            #pragma unroll
            for (int mi = 0; mi < 4; mi++) {
                int r0 = wm + mi * 16 + (lane >> 2);
                #pragma unroll
                for (int ni = 0; ni < 4; ni++) {
                    int c = ni * 8 + 2 * (lane & 3);
                    ep[r0 * 36 + c]           = acc[mi][ni][0];
                    ep[r0 * 36 + c + 1]       = acc[mi][ni][1];
                    ep[(r0 + 8) * 36 + c]     = acc[mi][ni][2];
                    ep[(r0 + 8) * 36 + c + 1] = acc[mi][ni][3];
                }
            }
        }
        __syncthreads();
        #pragma unroll
        for (int i = 0; i < 4; i++) {
            int idx = tid + i * 256;               // 0..1023
            int r = idx >> 3, c4 = idx & 7;
            int gc = n0 + p * 32 + c4 * 4;
            float4 v = *reinterpret_cast<float4*>(&ep[r * 36 + c4 * 4]);
            float4 b4 = *reinterpret_cast<const float4*>(bias + gc);
            float vv[4] = {v.x + b4.x, v.y + b4.y, v.z + b4.z, v.w + b4.w};
            if (act == 1) {
                #pragma unroll
                for (int j = 0; j < 4; j++)
                    if (gc + j < 1024) vv[j] = tanhf(vv[j]);
            } else if (act == 2) {
                #pragma unroll
                for (int j = 0; j < 4; j++)
                    vv[j] = 0.5f * vv[j] * (1.f + erff(vv[j] * 0.70710678118654752f));
            }
            size_t o = (size_t)(m0 + r) * N + gc;
            if (res) {
                float4 r4 = *reinterpret_cast<const float4*>(res + o);
                vv[0] += r4.x; vv[1] += r4.y; vv[2] += r4.z; vv[3] += r4.w;
            }
            if (outF) {
                float4 w = {vv[0], vv[1], vv[2], vv[3]};
                *reinterpret_cast<float4*>(outF + o) = w;
            }
            if (outHi) {
                #pragma unroll
                for (int j = 0; j < 4; j++) {
                    __nv_bfloat16 h = __float2bfloat16(vv[j]);
                    outHi[o + j] = h;
                    outLo[o + j] = __float2bfloat16(vv[j] - __bfloat162float(h));
                }
            }
        }
        __syncthreads();
    }
}

// ============= recurrence: 3-phase chunked affine scan ======================
__global__ void scan1()
{
    int c = blockIdx.x;
    int q = blockIdx.y * 256 + threadIdx.x;
    int b = q >> 10, jj = q & 1023;
    const float* base = g_abw + (size_t)b * LL * 3072 + jj;
    int l0 = c * 32;
    float A = 1.f, C = 0.f;
    #pragma unroll 8
    for (int i = 0; i < 32; i++) {
        float a  = base[(size_t)(l0 + i) * 3072];
        float bv = base[(size_t)(l0 + i) * 3072 + 1024];
        C = fmaf(a, C, bv * bv);
        A *= a;
    }
    g_scanA[c * MTOK + q] = A;
    g_scanC[c * MTOK + q] = C;
}

__global__ void scan2()
{
    int q = blockIdx.x * 256 + threadIdx.x;
    float h = 0.f;
    #pragma unroll
    for (int c = 0; c < 32; c++) {
        g_hst[c * MTOK + q] = h;
        h = fmaf(g_scanA[c * MTOK + q], h, g_scanC[c * MTOK + q]);
    }
}

__global__ void scan3()
{
    int c = blockIdx.x;
    int q = blockIdx.y * 256 + threadIdx.x;
    int b = q >> 10, jj = q & 1023;
    const float* base = g_abw + (size_t)b * LL * 3072 + jj;
    float* hsp = g_hs + b * HID + jj;
    float h = g_hst[c * MTOK + q];
    int l0 = c * 32;
    #pragma unroll 8
    for (int i = 0; i < 32; i++) {
        int l = l0 + i;
        float a  = base[(size_t)l * 3072];
        float bv = base[(size_t)l * 3072 + 1024];
        h = fmaf(a, h, bv * bv);
        hsp[(size_t)l * (BB * HID)] = h;
    }
}

// ============= per-head C projection + gating ===============================
__global__ void __launch_bounds__(256)
headmm(const float* __restrict__ Cw, const float* __restrict__ Cb)
{
    __shared__ float S [64][65];
    __shared__ float Cs[64][65];
    int tile = blockIdx.x, h = blockIdx.y;
    int t0 = tile * 64;
    int b = t0 >> 10, l0 = t0 & 1023;
    int tid = threadIdx.x;

    for (int i = tid; i < 64 * 64; i += 256) {
        int r = i >> 6, c = i & 63;
        S [r][c] = g_hs[(size_t)(l0 + r) * (BB * HID) + b * HID + h * 64 + c];
        Cs[r][c] = Cw[(size_t)h * 4096 + i];
    }
    __syncthreads();

    int ty = tid >> 4, tx = tid & 15;
    float acc[4][4] = {};
    for (int k = 0; k < 64; k++) {
        float ra[4], rb[4];
        #pragma unroll
        for (int i = 0; i < 4; i++) ra[i] = S[ty * 4 + i][k];
        #pragma unroll
        for (int j = 0; j < 4; j++) rb[j] = Cs[k][tx * 4 + j];
        #pragma unroll
        for (int i = 0; i < 4; i++)
            #pragma unroll
            for (int j = 0; j < 4; j++)
                acc[i][j] = fmaf(ra[i], rb[j], acc[i][j]);
    }

    #pragma unroll
    for (int i = 0; i < 4; i++) {
        int t = t0 + ty * 4 + i;
        #pragma unroll
        for (int j = 0; j < 4; j++) {
            int col = h * 64 + tx * 4 + j;
            float v = acc[i][j] + Cb[col];
            v *= g_abw[(size_t)t * 3072 + 2048 + col];
            g_z[(size_t)t * HID + col] = v;
        }
    }
}

// ============= u = z + LN(z), plus bf16 split of u ==========================
__device__ __forceinline__ float warpsum(float v)
{
    #pragma unroll
    for (int o = 16; o; o >>= 1) v += __shfl_xor_sync(0xffffffffu, v, o);
    return v;
}

__global__ void __launch_bounds__(256)
ln_resid(const float* __restrict__ gamma, const float* __restrict__ beta)
{
    int t = blockIdx.x;
    int tid = threadIdx.x;
    const float* z = g_z + (size_t)t * HID;
    float xv[4];
    float s = 0.f, s2 = 0.f;
    #pragma unroll
    for (int k = 0; k < 4; k++) {
        float v = z[tid + 256 * k];
        xv[k] = v; s += v; s2 += v * v;
    }
    __shared__ float sh[2][8];
    s = warpsum(s); s2 = warpsum(s2);
    int w = tid >> 5, ln = tid & 31;
    if (!ln) { sh[0][w] = s; sh[1][w] = s2; }
    __syncthreads();
    if (tid < 32) {
        float a  = (ln < 8) ? sh[0][ln] : 0.f;
        float b2 = (ln < 8) ? sh[1][ln] : 0.f;
        a = warpsum(a); b2 = warpsum(b2);
        if (!ln) { sh[0][0] = a; sh[1][0] = b2; }
    }
    __syncthreads();
    float mu   = sh[0][0] * (1.f / 1024.f);
    float var  = sh[1][0] * (1.f / 1024.f) - mu * mu;
    float rstd = rsqrtf(var + 1e-5f);
    float* u = g_u + (size_t)t * HID;
    #pragma unroll
    for (int k = 0; k < 4; k++) {
        int c = tid + 256 * k;
        float v = xv[k];
        float uu = v + (v - mu) * rstd * gamma[c] + beta[c];
        u[c] = uu;
        __nv_bfloat16 h = __float2bfloat16(uu);
        g_uH[(size_t)t * HID + c] = h;
        g_uL[(size_t)t * HID + c] = __float2bfloat16(uu - __bfloat162float(h));
    }
}

// ===================== launch ===============================================
extern "C" void kernel_launch(void* const* d_in, const int* in_sizes, int n_in,
                              void* d_out, int out_size)
{
    const int*   x      = (const int*)  d_in[0];
    const float* embed  = (const float*)d_in[1];
    const float* Wa     = (const float*)d_in[2];
    const float* ba     = (const float*)d_in[3];
    const float* Wb     = (const float*)d_in[4];
    const float* bb     = (const float*)d_in[5];
    const float* Wo     = (const float*)d_in[6];
    const float* bo     = (const float*)d_in[7];
    const float* Cw     = (const float*)d_in[8];
    const float* Cb     = (const float*)d_in[9];
    const float* proj_w = (const float*)d_in[10];
    const float* proj_b = (const float*)d_in[11];
    const float* gamma  = (const float*)d_in[12];
    const float* beta   = (const float*)d_in[13];
    const float* ffn1_w = (const float*)d_in[14];
    const float* ffn1_b = (const float*)d_in[15];
    const float* ffn2_w = (const float*)d_in[16];
    const float* ffn2_b = (const float*)d_in[17];
    const float* out_w  = (const float*)d_in[18];
    const float* out_b  = (const float*)d_in[19];
    float* out = (float*)d_out;
    (void)in_sizes; (void)n_in; (void)out_size;

    cudaFuncSetAttribute(gemm_tc, cudaFuncAttributeMaxDynamicSharedMemorySize, GSMEM);

    float *abw, *uf;
    __nv_bfloat16 *embH, *embL, *uH, *uL, *midH, *midL, *houtH, *houtL, *pH, *pL;
    __nv_bfloat16 *W3tH, *W3tL, *f1tH, *f1tL, *f2tH, *f2tL, *pjtH, *pjtL, *owtH, *owtL;
    float *b3p;
    cudaGetSymbolAddress((void**)&abw,   g_abw);
    cudaGetSymbolAddress((void**)&uf,    g_u);
    cudaGetSymbolAddress((void**)&b3p,   g_b3);
    cudaGetSymbolAddress((void**)&embH,  g_embH);  cudaGetSymbolAddress((void**)&embL,  g_embL);
    cudaGetSymbolAddress((void**)&uH,    g_uH);    cudaGetSymbolAddress((void**)&uL,    g_uL);
    cudaGetSymbolAddress((void**)&midH,  g_midH);  cudaGetSymbolAddress((void**)&midL,  g_midL);
    cudaGetSymbolAddress((void**)&houtH, g_houtH); cudaGetSymbolAddress((void**)&houtL, g_houtL);
    cudaGetSymbolAddress((void**)&pH,    g_pH);    cudaGetSymbolAddress((void**)&pL,    g_pL);
    cudaGetSymbolAddress((void**)&W3tH,  g_W3tH);  cudaGetSymbolAddress((void**)&W3tL,  g_W3tL);
    cudaGetSymbolAddress((void**)&f1tH,  g_f1tH);  cudaGetSymbolAddress((void**)&f1tL,  g_f1tL);
    cudaGetSymbolAddress((void**)&f2tH,  g_f2tH);  cudaGetSymbolAddress((void**)&f2tL,  g_f2tL);
    cudaGetSymbolAddress((void**)&pjtH,  g_pjtH);  cudaGetSymbolAddress((void**)&pjtL,  g_pjtL);
    cudaGetSymbolAddress((void**)&owtH,  g_owtH);  cudaGetSymbolAddress((void**)&owtL,  g_owtL);

    dim3 tb(32, 8);
    // weight transposes + splits
    tsplit<<<dim3(32, 2, 16), tb>>>(Wa, W3tH,               W3tL,               1024, 64, (long)EE * DD, 64);
    tsplit<<<dim3(32, 2, 16), tb>>>(Wb, W3tH + 1024 * 1024, W3tL + 1024 * 1024, 1024, 64, (long)EE * DD, 64);
    tsplit<<<dim3(32, 2, 16), tb>>>(Wo, W3tH + 2048 * 1024, W3tL + 2048 * 1024, 1024, 64, (long)EE * DD, 64);
    tsplit<<<dim3(32, 128, 1), tb>>>(ffn1_w, f1tH, f1tL, 1024, 4096, 0, 0);
    tsplit<<<dim3(128, 32, 1), tb>>>(ffn2_w, f2tH, f2tL, 4096, 1024, 0, 0);
    tsplit<<<dim3(32, 32, 1),  tb>>>(proj_w, pjtH, pjtL, 1024, 1024, 0, 0);
    tsplit<<<dim3(32, 1000, 1), tb>>>(out_w, owtH, owtL, 1024, VV, 0, 0);
    pack_b3k<<<4, 256>>>(ba, bb, bo);

    // embedding gather + split
    gather_emb<<<(MTOK * 256) / 256, 256>>>(x, embed);

    // abw = [tanh(emb@Wa+ba) | emb@Wb+bb | emb@Wo+bo]   (fp32 out)
    gemm_tc<<<dim3(16, 24), 256, GSMEM>>>(embH, embL, W3tH, W3tL, b3p,
                                          nullptr, abw, nullptr, nullptr, 3072, 1024, 1);
    // recurrence
    scan1<<<dim3(32, 8), 256>>>();
    scan2<<<8, 256>>>();
    scan3<<<dim3(32, 8), 256>>>();
    // per-head C projection + gating
    headmm<<<dim3(MTOK / 64, HH), 256>>>(Cw, Cb);
    // u = z + LN(z), split
    ln_resid<<<MTOK, 256>>>(gamma, beta);
    // FFN1 + gelu -> mid (split only)
    gemm_tc<<<dim3(16, 32), 256, GSMEM>>>(uH, uL, f1tH, f1tL, ffn1_b,
                                          nullptr, nullptr, midH, midL, 4096, 1024, 2);
    // FFN2 + residual u -> hout (split only)
    gemm_tc<<<dim3(16, 8), 256, GSMEM>>>(midH, midL, f2tH, f2tL, ffn2_b,
                                         uf, nullptr, houtH, houtL, 1024, 4096, 0);
    // proj -> p (split only)
    gemm_tc<<<dim3(16, 8), 256, GSMEM>>>(houtH, houtL, pjtH, pjtL, proj_b,
                                         nullptr, nullptr, pH, pL, 1024, 1024, 0);
    // logits (fp32 out)
    gemm_tc<<<dim3(16, 250), 256, GSMEM>>>(pH, pL, owtH, owtL, out_b,
                                           nullptr, out, nullptr, nullptr, VV, 1024, 0);
}

// round 10
// speedup vs baseline: 3.0105x; 1.0326x over previous
#include <cuda_runtime.h>
#include <cuda_bf16.h>
#include <math.h>
#include <stdint.h>

// Problem constants
#define BB   2
#define LL   1024
#define VV   32000
#define EE   1024
#define HH   16
#define DD   64
#define HID  1024
#define MTOK (BB*LL)      // 2048 tokens

// ===================== helpers (plain sm_80+ PTX only) ======================
__device__ __forceinline__ uint32_t smem_u32(const void* p) {
    uint32_t a;
    asm("{ .reg .u64 t; cvta.to.shared.u64 t, %1; cvt.u32.u64 %0, t; }"
        : "=r"(a) : "l"(p));
    return a;
}
#define SMEM_SWIZZLE_128B(o) ((o) ^ (((o) >> 3) & 0x70))

#define CP_ASYNC16(dst, src) \
    asm volatile("cp.async.cg.shared.global [%0], [%1], 16;" \
                 :: "r"(dst), "l"(src) : "memory")
#define CP_COMMIT() asm volatile("cp.async.commit_group;" ::: "memory")
#define CP_WAIT1()  asm volatile("cp.async.wait_group 1;" ::: "memory")
#define CP_WAIT0()  asm volatile("cp.async.wait_group 0;" ::: "memory")

#define LDSM_X4(d, addr) \
    asm volatile("ldmatrix.sync.aligned.m8n8.x4.shared.b16 {%0,%1,%2,%3}, [%4];" \
                 : "=r"((d)[0]), "=r"((d)[1]), "=r"((d)[2]), "=r"((d)[3]) : "r"(addr))

#define MMA_BF16(c, a, b0_, b1_) \
    asm volatile("mma.sync.aligned.m16n8k16.row.col.f32.bf16.bf16.f32 " \
                 "{%0,%1,%2,%3}, {%4,%5,%6,%7}, {%8,%9}, {%0,%1,%2,%3};" \
                 : "+f"((c)[0]), "+f"((c)[1]), "+f"((c)[2]), "+f"((c)[3]) \
                 : "r"((a)[0]), "r"((a)[1]), "r"((a)[2]), "r"((a)[3]), \
                   "r"(b0_), "r"(b1_))

// ===================== scratch (device globals; no allocation) ==============
__device__ float g_abw  [MTOK * 3 * HID];
__device__ float g_hs   [MTOK * HID];
__device__ float g_z    [MTOK * HID];
__device__ float g_u    [MTOK * HID];
__device__ float g_b3   [3 * HID];
__device__ float g_scanA[32 * MTOK];
__device__ float g_scanC[32 * MTOK];
__device__ float g_hst  [32 * MTOK];

__device__ __nv_bfloat16 g_embH [MTOK * EE],      g_embL [MTOK * EE];
__device__ __nv_bfloat16 g_uH   [MTOK * HID],     g_uL   [MTOK * HID];
__device__ __nv_bfloat16 g_midH [MTOK * 4 * HID], g_midL [MTOK * 4 * HID];
__device__ __nv_bfloat16 g_houtH[MTOK * HID],     g_houtL[MTOK * HID];
__device__ __nv_bfloat16 g_pH   [MTOK * HID],     g_pL   [MTOK * HID];
__device__ __nv_bfloat16 g_W3tH [3 * HID * EE],   g_W3tL [3 * HID * EE];
__device__ __nv_bfloat16 g_f1tH [4 * HID * HID],  g_f1tL [4 * HID * HID];
__device__ __nv_bfloat16 g_f2tH [4 * HID * HID],  g_f2tL [4 * HID * HID];
__device__ __nv_bfloat16 g_pjtH [HID * HID],      g_pjtL [HID * HID];
__device__ __nv_bfloat16 g_owtH [(size_t)VV * HID], g_owtL[(size_t)VV * HID];

// ============= transpose + bf16 split: in[K,N] f32 -> out[N,K] hi/lo ========
// 64(k) x 32(n) tiles; bfloat162 writes (full 128B lines per warp).
__global__ void tsplit(const float* __restrict__ in, __nv_bfloat16* __restrict__ oh,
                       __nv_bfloat16* __restrict__ ol, int K, int N,
                       long inZ, long outZrow)
{
    __shared__ float s[64][33];
    int k0 = blockIdx.x * 64, n0 = blockIdx.y * 32, z = blockIdx.z;
    in += (size_t)z * inZ;
    size_t rbase = (size_t)z * outZrow + n0;
    int tx = threadIdx.x, ty = threadIdx.y;       // 32 x 8
    #pragma unroll
    for (int i = 0; i < 8; i++)
        s[ty + 8 * i][tx] = in[(size_t)(k0 + ty + 8 * i) * N + n0 + tx];
    __syncthreads();
    int tid = ty * 32 + tx;
    #pragma unroll
    for (int j = 0; j < 4; j++) {
        int id = tid + 256 * j;                   // 0..1023
        int n = id >> 5, kp = id & 31;            // n row, k-pair
        float v0 = s[2 * kp][n], v1 = s[2 * kp + 1][n];
        __nv_bfloat16 h0 = __float2bfloat16(v0), h1 = __float2bfloat16(v1);
        __nv_bfloat162 hv; hv.x = h0; hv.y = h1;
        __nv_bfloat162 lv;
        lv.x = __float2bfloat16(v0 - __bfloat162float(h0));
        lv.y = __float2bfloat16(v1 - __bfloat162float(h1));
        size_t o = (rbase + n) * (size_t)K + k0 + 2 * kp;
        *reinterpret_cast<__nv_bfloat162*>(oh + o) = hv;
        *reinterpret_cast<__nv_bfloat162*>(ol + o) = lv;
    }
}

__global__ void pack_b3k(const float* __restrict__ ba, const float* __restrict__ bb,
                         const float* __restrict__ bo)
{
    int j = blockIdx.x * 256 + threadIdx.x;
    g_b3[j] = ba[j]; g_b3[1024 + j] = bb[j]; g_b3[2048 + j] = bo[j];
}

// ============= embedding gather + bf16 split ================================
__global__ void gather_emb(const int* __restrict__ x, const float* __restrict__ embed)
{
    int i = blockIdx.x * blockDim.x + threadIdx.x;   // over MTOK*256 float4s
    int t = i >> 8, c4 = i & 255;
    int tok = x[t];
    float4 v = reinterpret_cast<const float4*>(embed + (size_t)tok * EE)[c4];
    size_t o = (size_t)t * EE + c4 * 4;
    float vv[4] = {v.x, v.y, v.z, v.w};
    #pragma unroll
    for (int j = 0; j < 4; j++) {
        __nv_bfloat16 h = __float2bfloat16(vv[j]);
        g_embH[o + j] = h;
        g_embL[o + j] = __float2bfloat16(vv[j] - __bfloat162float(h));
    }
}

// ===================== split-bf16 HMMA GEMM =================================
// D[M,N] = Ahi@Bhi^T + Ahi@Blo^T + Alo@Bhi^T  (fp32 accum in registers)
// Block 128x128, K-chunk 64, 3-stage cp.async pipeline (3 x 64KB stages),
// single __syncthreads per chunk, single-pass epilogue.
#define STAGE_BYTES 65536
#define GSMEM (3 * STAGE_BYTES)

__device__ __forceinline__ void load_chunk(
    uint32_t sdst, const __nv_bfloat16* __restrict__ Ahi,
    const __nv_bfloat16* __restrict__ Alo, const __nv_bfloat16* __restrict__ Bhi,
    const __nv_bfloat16* __restrict__ Blo, int m0, int n0, int K, int k0, int tid)
{
    #pragma unroll
    for (int t = 0; t < 4; t++) {
        int idx = tid + t * 256;               // 0..1023 16B lines per tile
        int r = idx >> 3, c8 = idx & 7;
        uint32_t off = SMEM_SWIZZLE_128B(r * 128 + c8 * 16);
        CP_ASYNC16(sdst + off,         Ahi + (size_t)(m0 + r) * K + k0 + c8 * 8);
        CP_ASYNC16(sdst + 16384 + off, Alo + (size_t)(m0 + r) * K + k0 + c8 * 8);
        CP_ASYNC16(sdst + 32768 + off, Bhi + (size_t)(n0 + r) * K + k0 + c8 * 8);
        CP_ASYNC16(sdst + 49152 + off, Blo + (size_t)(n0 + r) * K + k0 + c8 * 8);
    }
}

__global__ void __launch_bounds__(256)
gemm_tc(const __nv_bfloat16* __restrict__ Ahi, const __nv_bfloat16* __restrict__ Alo,
        const __nv_bfloat16* __restrict__ Bhi, const __nv_bfloat16* __restrict__ Blo,
        const float* __restrict__ bias, const float* __restrict__ res,
        float* __restrict__ outF, __nv_bfloat16* __restrict__ outHi,
        __nv_bfloat16* __restrict__ outLo, int N, int K, int act)
{
    extern __shared__ char smem[];
    const int tid = threadIdx.x;
    const int wid = tid >> 5, lane = tid & 31;
    const int m0 = blockIdx.x * 128, n0 = blockIdx.y * 128;
    const int wm = (wid & 1) * 64, wn = (wid >> 1) * 32;
    const uint32_t sb = smem_u32(smem);

    float acc[4][4][4];
    #pragma unroll
    for (int mi = 0; mi < 4; mi++)
        #pragma unroll
        for (int ni = 0; ni < 4; ni++)
            #pragma unroll
            for (int e = 0; e < 4; e++) acc[mi][ni][e] = 0.f;

    const int nch = K / 64;
    load_chunk(sb, Ahi, Alo, Bhi, Blo, m0, n0, K, 0, tid);
    CP_COMMIT();
    load_chunk(sb + STAGE_BYTES, Ahi, Alo, Bhi, Blo, m0, n0, K, 64, tid);
    CP_COMMIT();

    int stage = 0;
    for (int it = 0; it < nch; it++) {
        if (it + 1 < nch) { CP_WAIT1(); } else { CP_WAIT0(); }
        __syncthreads();     // chunk 'it' visible; all warps done reading stage being refilled
        if (it + 2 < nch) {
            int s2 = stage + 2; if (s2 >= 3) s2 -= 3;
            load_chunk(sb + s2 * STAGE_BYTES, Ahi, Alo, Bhi, Blo, m0, n0, K,
                       (it + 2) * 64, tid);
            CP_COMMIT();
        }

        const uint32_t st = sb + stage * STAGE_BYTES;
        const uint32_t tA1 = st, tA2 = st + 16384, tB1 = st + 32768, tB2 = st + 49152;
        const int lr = lane & 15, lg = (lane >> 4) << 4;

        #pragma unroll
        for (int kk = 0; kk < 4; kk++) {
            uint32_t a1[4][4], a2[4][4], b1[2][4], b2[2][4];
            #pragma unroll
            for (int mi = 0; mi < 4; mi++) {
                uint32_t off = SMEM_SWIZZLE_128B((wm + mi * 16 + lr) * 128 + kk * 32 + lg);
                LDSM_X4(a1[mi], tA1 + off);
                LDSM_X4(a2[mi], tA2 + off);
            }
            #pragma unroll
            for (int pi = 0; pi < 2; pi++) {
                uint32_t off = SMEM_SWIZZLE_128B((wn + pi * 16 + lr) * 128 + kk * 32 + lg);
                LDSM_X4(b1[pi], tB1 + off);
                LDSM_X4(b2[pi], tB2 + off);
            }
            #pragma unroll
            for (int mi = 0; mi < 4; mi++) {
                #pragma unroll
                for (int pi = 0; pi < 2; pi++) {
                    MMA_BF16(acc[mi][2 * pi],     a1[mi], b1[pi][0], b1[pi][2]);
                    MMA_BF16(acc[mi][2 * pi + 1], a1[mi], b1[pi][1], b1[pi][3]);
                    MMA_BF16(acc[mi][2 * pi],     a1[mi], b2[pi][0], b2[pi][2]);
                    MMA_BF16(acc[mi][2 * pi + 1], a1[mi], b2[pi][1], b2[pi][3]);
                    MMA_BF16(acc[mi][2 * pi],     a2[mi], b1[pi][0], b1[pi][2]);
                    MMA_BF16(acc[mi][2 * pi + 1], a2[mi], b1[pi][1], b1[pi][3]);
                }
            }
        }
        if (++stage == 3) stage = 0;
    }
    __syncthreads();    // lagging warps finish before epilogue overwrites smem

    // ---- epilogue: single pass through [128][132] fp32 smem tile ----
    float* ep = reinterpret_cast<float*>(smem);
    #pragma unroll
    for (int mi = 0; mi < 4; mi++) {
        int r0 = wm + mi * 16 + (lane >> 2);
        #pragma unroll
        for (int ni = 0; ni < 4; ni++) {
            int c = wn + ni * 8 + 2 * (lane & 3);
            ep[r0 * 132 + c]           = acc[mi][ni][0];
            ep[r0 * 132 + c + 1]       = acc[mi][ni][1];
            ep[(r0 + 8) * 132 + c]     = acc[mi][ni][2];
            ep[(r0 + 8) * 132 + c + 1] = acc[mi][ni][3];
        }
    }
    __syncthreads();
    #pragma unroll
    for (int i = 0; i < 16; i++) {
        int idx = tid + i * 256;                 // 0..4095 float4s
        int r = idx >> 5, c4 = idx & 31;
        int gc = n0 + c4 * 4;
        float4 v = *reinterpret_cast<float4*>(&ep[r * 132 + c4 * 4]);
        float4 b4 = *reinterpret_cast<const float4*>(bias + gc);
        float vv[4] = {v.x + b4.x, v.y + b4.y, v.z + b4.z, v.w + b4.w};
        if (act == 1) {
            #pragma unroll
            for (int j = 0; j < 4; j++)
                if (gc + j < 1024) vv[j] = tanhf(vv[j]);
        } else if (act == 2) {
            #pragma unroll
            for (int j = 0; j < 4; j++)
                vv[j] = 0.5f * vv[j] * (1.f + erff(vv[j] * 0.70710678118654752f));
        }
        size_t o = (size_t)(m0 + r) * N + gc;
        if (res) {
            float4 r4 = *reinterpret_cast<const float4*>(res + o);
            vv[0] += r4.x; vv[1] += r4.y; vv[2] += r4.z; vv[3] += r4.w;
        }
        if (outF) {
            float4 w = {vv[0], vv[1], vv[2], vv[3]};
            *reinterpret_cast<float4*>(outF + o) = w;
        }
        if (outHi) {
            #pragma unroll
            for (int j = 0; j < 4; j++) {
                __nv_bfloat16 h = __float2bfloat16(vv[j]);
                outHi[o + j] = h;
                outLo[o + j] = __float2bfloat16(vv[j] - __bfloat162float(h));
            }
        }
    }
}

// ============= recurrence: 3-phase chunked affine scan ======================
__global__ void scan1()
{
    int c = blockIdx.x;
    int q = blockIdx.y * 256 + threadIdx.x;
    int b = q >> 10, jj = q & 1023;
    const float* base = g_abw + (size_t)b * LL * 3072 + jj;
    int l0 = c * 32;
    float A = 1.f, C = 0.f;
    #pragma unroll 8
    for (int i = 0; i < 32; i++) {
        float a  = base[(size_t)(l0 + i) * 3072];
        float bv = base[(size_t)(l0 + i) * 3072 + 1024];
        C = fmaf(a, C, bv * bv);
        A *= a;
    }
    g_scanA[c * MTOK + q] = A;
    g_scanC[c * MTOK + q] = C;
}

__global__ void scan2()
{
    int q = blockIdx.x * 256 + threadIdx.x;
    float h = 0.f;
    #pragma unroll
    for (int c = 0; c < 32; c++) {
        g_hst[c * MTOK + q] = h;
        h = fmaf(g_scanA[c * MTOK + q], h, g_scanC[c * MTOK + q]);
    }
}

__global__ void scan3()
{
    int c = blockIdx.x;
    int q = blockIdx.y * 256 + threadIdx.x;
    int b = q >> 10, jj = q & 1023;
    const float* base = g_abw + (size_t)b * LL * 3072 + jj;
    float* hsp = g_hs + b * HID + jj;
    float h = g_hst[c * MTOK + q];
    int l0 = c * 32;
    #pragma unroll 8
    for (int i = 0; i < 32; i++) {
        int l = l0 + i;
        float a  = base[(size_t)l * 3072];
        float bv = base[(size_t)l * 3072 + 1024];
        h = fmaf(a, h, bv * bv);
        hsp[(size_t)l * (BB * HID)] = h;
    }
}

// ============= per-head C projection + gating ===============================
__global__ void __launch_bounds__(256)
headmm(const float* __restrict__ Cw, const float* __restrict__ Cb)
{
    __shared__ float S [64][65];
    __shared__ float Cs[64][65];
    int tile = blockIdx.x, h = blockIdx.y;
    int t0 = tile * 64;
    int b = t0 >> 10, l0 = t0 & 1023;
    int tid = threadIdx.x;

    for (int i = tid; i < 64 * 64; i += 256) {
        int r = i >> 6, c = i & 63;
        S [r][c] = g_hs[(size_t)(l0 + r) * (BB * HID) + b * HID + h * 64 + c];
        Cs[r][c] = Cw[(size_t)h * 4096 + i];
    }
    __syncthreads();

    int ty = tid >> 4, tx = tid & 15;
    float acc[4][4] = {};
    for (int k = 0; k < 64; k++) {
        float ra[4], rb[4];
        #pragma unroll
        for (int i = 0; i < 4; i++) ra[i] = S[ty * 4 + i][k];
        #pragma unroll
        for (int j = 0; j < 4; j++) rb[j] = Cs[k][tx * 4 + j];
        #pragma unroll
        for (int i = 0; i < 4; i++)
            #pragma unroll
            for (int j = 0; j < 4; j++)
                acc[i][j] = fmaf(ra[i], rb[j], acc[i][j]);
    }

    #pragma unroll
    for (int i = 0; i < 4; i++) {
        int t = t0 + ty * 4 + i;
        #pragma unroll
        for (int j = 0; j < 4; j++) {
            int col = h * 64 + tx * 4 + j;
            float v = acc[i][j] + Cb[col];
            v *= g_abw[(size_t)t * 3072 + 2048 + col];
            g_z[(size_t)t * HID + col] = v;
        }
    }
}

// ============= u = z + LN(z), plus bf16 split of u ==========================
__device__ __forceinline__ float warpsum(float v)
{
    #pragma unroll
    for (int o = 16; o; o >>= 1) v += __shfl_xor_sync(0xffffffffu, v, o);
    return v;
}

__global__ void __launch_bounds__(256)
ln_resid(const float* __restrict__ gamma, const float* __restrict__ beta)
{
    int t = blockIdx.x;
    int tid = threadIdx.x;
    const float* z = g_z + (size_t)t * HID;
    float xv[4];
    float s = 0.f, s2 = 0.f;
    #pragma unroll
    for (int k = 0; k < 4; k++) {
        float v = z[tid + 256 * k];
        xv[k] = v; s += v; s2 += v * v;
    }
    __shared__ float sh[2][8];
    s = warpsum(s); s2 = warpsum(s2);
    int w = tid >> 5, ln = tid & 31;
    if (!ln) { sh[0][w] = s; sh[1][w] = s2; }
    __syncthreads();
    if (tid < 32) {
        float a  = (ln < 8) ? sh[0][ln] : 0.f;
        float b2 = (ln < 8) ? sh[1][ln] : 0.f;
        a = warpsum(a); b2 = warpsum(b2);
        if (!ln) { sh[0][0] = a; sh[1][0] = b2; }
    }
    __syncthreads();
    float mu   = sh[0][0] * (1.f / 1024.f);
    float var  = sh[1][0] * (1.f / 1024.f) - mu * mu;
    float rstd = rsqrtf(var + 1e-5f);
    float* u = g_u + (size_t)t * HID;
    #pragma unroll
    for (int k = 0; k < 4; k++) {
        int c = tid + 256 * k;
        float v = xv[k];
        float uu = v + (v - mu) * rstd * gamma[c] + beta[c];
        u[c] = uu;
        __nv_bfloat16 h = __float2bfloat16(uu);
        g_uH[(size_t)t * HID + c] = h;
        g_uL[(size_t)t * HID + c] = __float2bfloat16(uu - __bfloat162float(h));
    }
}

// ===================== launch ===============================================
extern "C" void kernel_launch(void* const* d_in, const int* in_sizes, int n_in,
                              void* d_out, int out_size)
{
    const int*   x      = (const int*)  d_in[0];
    const float* embed  = (const float*)d_in[1];
    const float* Wa     = (const float*)d_in[2];
    const float* ba     = (const float*)d_in[3];
    const float* Wb     = (const float*)d_in[4];
    const float* bb     = (const float*)d_in[5];
    const float* Wo     = (const float*)d_in[6];
    const float* bo     = (const float*)d_in[7];
    const float* Cw     = (const float*)d_in[8];
    const float* Cb     = (const float*)d_in[9];
    const float* proj_w = (const float*)d_in[10];
    const float* proj_b = (const float*)d_in[11];
    const float* gamma  = (const float*)d_in[12];
    const float* beta   = (const float*)d_in[13];
    const float* ffn1_w = (const float*)d_in[14];
    const float* ffn1_b = (const float*)d_in[15];
    const float* ffn2_w = (const float*)d_in[16];
    const float* ffn2_b = (const float*)d_in[17];
    const float* out_w  = (const float*)d_in[18];
    const float* out_b  = (const float*)d_in[19];
    float* out = (float*)d_out;
    (void)in_sizes; (void)n_in; (void)out_size;

    cudaFuncSetAttribute(gemm_tc, cudaFuncAttributeMaxDynamicSharedMemorySize, GSMEM);

    float *abw, *uf;
    __nv_bfloat16 *embH, *embL, *uH, *uL, *midH, *midL, *houtH, *houtL, *pH, *pL;
    __nv_bfloat16 *W3tH, *W3tL, *f1tH, *f1tL, *f2tH, *f2tL, *pjtH, *pjtL, *owtH, *owtL;
    float *b3p;
    cudaGetSymbolAddress((void**)&abw,   g_abw);
    cudaGetSymbolAddress((void**)&uf,    g_u);
    cudaGetSymbolAddress((void**)&b3p,   g_b3);
    cudaGetSymbolAddress((void**)&embH,  g_embH);  cudaGetSymbolAddress((void**)&embL,  g_embL);
    cudaGetSymbolAddress((void**)&uH,    g_uH);    cudaGetSymbolAddress((void**)&uL,    g_uL);
    cudaGetSymbolAddress((void**)&midH,  g_midH);  cudaGetSymbolAddress((void**)&midL,  g_midL);
    cudaGetSymbolAddress((void**)&houtH, g_houtH); cudaGetSymbolAddress((void**)&houtL, g_houtL);
    cudaGetSymbolAddress((void**)&pH,    g_pH);    cudaGetSymbolAddress((void**)&pL,    g_pL);
    cudaGetSymbolAddress((void**)&W3tH,  g_W3tH);  cudaGetSymbolAddress((void**)&W3tL,  g_W3tL);
    cudaGetSymbolAddress((void**)&f1tH,  g_f1tH);  cudaGetSymbolAddress((void**)&f1tL,  g_f1tL);
    cudaGetSymbolAddress((void**)&f2tH,  g_f2tH);  cudaGetSymbolAddress((void**)&f2tL,  g_f2tL);
    cudaGetSymbolAddress((void**)&pjtH,  g_pjtH);  cudaGetSymbolAddress((void**)&pjtL,  g_pjtL);
    cudaGetSymbolAddress((void**)&owtH,  g_owtH);  cudaGetSymbolAddress((void**)&owtL,  g_owtL);

    dim3 tb(32, 8);
    // weight transposes + splits (in[K,N] -> out[N,K] hi/lo), 64x32 tiles
    tsplit<<<dim3(16, 2, 16), tb>>>(Wa, W3tH,               W3tL,               1024, 64, (long)EE * DD, 64);
    tsplit<<<dim3(16, 2, 16), tb>>>(Wb, W3tH + 1024 * 1024, W3tL + 1024 * 1024, 1024, 64, (long)EE * DD, 64);
    tsplit<<<dim3(16, 2, 16), tb>>>(Wo, W3tH + 2048 * 1024, W3tL + 2048 * 1024, 1024, 64, (long)EE * DD, 64);
    tsplit<<<dim3(16, 128, 1), tb>>>(ffn1_w, f1tH, f1tL, 1024, 4096, 0, 0);
    tsplit<<<dim3(64, 32, 1),  tb>>>(ffn2_w, f2tH, f2tL, 4096, 1024, 0, 0);
    tsplit<<<dim3(16, 32, 1),  tb>>>(proj_w, pjtH, pjtL, 1024, 1024, 0, 0);
    tsplit<<<dim3(16, 1000, 1), tb>>>(out_w, owtH, owtL, 1024, VV, 0, 0);
    pack_b3k<<<4, 256>>>(ba, bb, bo);

    // embedding gather + split
    gather_emb<<<(MTOK * 256) / 256, 256>>>(x, embed);

    // abw = [tanh(emb@Wa+ba) | emb@Wb+bb | emb@Wo+bo]   (fp32 out)
    gemm_tc<<<dim3(16, 24), 256, GSMEM>>>(embH, embL, W3tH, W3tL, b3p,
                                          nullptr, abw, nullptr, nullptr, 3072, 1024, 1);
    // recurrence
    scan1<<<dim3(32, 8), 256>>>();
    scan2<<<8, 256>>>();
    scan3<<<dim3(32, 8), 256>>>();
    // per-head C projection + gating
    headmm<<<dim3(MTOK / 64, HH), 256>>>(Cw, Cb);
    // u = z + LN(z), split
    ln_resid<<<MTOK, 256>>>(gamma, beta);
    // FFN1 + gelu -> mid (split only)
    gemm_tc<<<dim3(16, 32), 256, GSMEM>>>(uH, uL, f1tH, f1tL, ffn1_b,
                                          nullptr, nullptr, midH, midL, 4096, 1024, 2);
    // FFN2 + residual u -> hout (split only)
    gemm_tc<<<dim3(16, 8), 256, GSMEM>>>(midH, midL, f2tH, f2tL, ffn2_b,
                                         uf, nullptr, houtH, houtL, 1024, 4096, 0);
    // proj -> p (split only)
    gemm_tc<<<dim3(16, 8), 256, GSMEM>>>(houtH, houtL, pjtH, pjtL, proj_b,
                                         nullptr, nullptr, pH, pL, 1024, 1024, 0);
    // logits (fp32 out)
    gemm_tc<<<dim3(16, 250), 256, GSMEM>>>(pH, pL, owtH, owtL, out_b,
                                           nullptr, out, nullptr, nullptr, VV, 1024, 0);
}

// round 11
// speedup vs baseline: 3.9233x; 1.3032x over previous
#include <cuda_runtime.h>
#include <cuda_bf16.h>
#include <cuda_fp16.h>
#include <math.h>
#include <stdint.h>

// Problem constants
#define BB   2
#define LL   1024
#define VV   32000
#define EE   1024
#define HH   16
#define DD   64
#define HID  1024
#define MTOK (BB*LL)      // 2048 tokens

// ===================== helpers (plain sm_80+ PTX only) ======================
__device__ __forceinline__ uint32_t smem_u32(const void* p) {
    uint32_t a;
    asm("{ .reg .u64 t; cvta.to.shared.u64 t, %1; cvt.u32.u64 %0, t; }"
        : "=r"(a) : "l"(p));
    return a;
}
#define SMEM_SWIZZLE_128B(o) ((o) ^ (((o) >> 3) & 0x70))

#define CP_ASYNC16(dst, src) \
    asm volatile("cp.async.cg.shared.global [%0], [%1], 16;" \
                 :: "r"(dst), "l"(src) : "memory")
#define CP_COMMIT() asm volatile("cp.async.commit_group;" ::: "memory")
#define CP_WAIT1()  asm volatile("cp.async.wait_group 1;" ::: "memory")
#define CP_WAIT0()  asm volatile("cp.async.wait_group 0;" ::: "memory")

#define LDSM_X4(d, addr) \
    asm volatile("ldmatrix.sync.aligned.m8n8.x4.shared.b16 {%0,%1,%2,%3}, [%4];" \
                 : "=r"((d)[0]), "=r"((d)[1]), "=r"((d)[2]), "=r"((d)[3]) : "r"(addr))

#define MMA_BF16(c, a, b0_, b1_) \
    asm volatile("mma.sync.aligned.m16n8k16.row.col.f32.bf16.bf16.f32 " \
                 "{%0,%1,%2,%3}, {%4,%5,%6,%7}, {%8,%9}, {%0,%1,%2,%3};" \
                 : "+f"((c)[0]), "+f"((c)[1]), "+f"((c)[2]), "+f"((c)[3]) \
                 : "r"((a)[0]), "r"((a)[1]), "r"((a)[2]), "r"((a)[3]), \
                   "r"(b0_), "r"(b1_))

#define MMA_F16(c, a, b0_, b1_) \
    asm volatile("mma.sync.aligned.m16n8k16.row.col.f32.f16.f16.f32 " \
                 "{%0,%1,%2,%3}, {%4,%5,%6,%7}, {%8,%9}, {%0,%1,%2,%3};" \
                 : "+f"((c)[0]), "+f"((c)[1]), "+f"((c)[2]), "+f"((c)[3]) \
                 : "r"((a)[0]), "r"((a)[1]), "r"((a)[2]), "r"((a)[3]), \
                   "r"(b0_), "r"(b1_))

// ===================== scratch (device globals; no allocation) ==============
__device__ float g_abw  [MTOK * 3 * HID];
__device__ float g_hs   [MTOK * HID];
__device__ float g_z    [MTOK * HID];
__device__ float g_u    [MTOK * HID];
__device__ float g_b3   [3 * HID];
__device__ float g_scanA[32 * MTOK];
__device__ float g_scanC[32 * MTOK];
__device__ float g_hst  [32 * MTOK];

// bf16 split (abw path only)
__device__ __nv_bfloat16 g_embH [MTOK * EE],    g_embL [MTOK * EE];
__device__ __nv_bfloat16 g_W3tH [3 * HID * EE], g_W3tL [3 * HID * EE];
// fp16 split activations (hi/lo) and unsplit fp16 weights
__device__ uint16_t g_uH16  [MTOK * HID],     g_uL16  [MTOK * HID];
__device__ uint16_t g_midH16[MTOK * 4 * HID], g_midL16[MTOK * 4 * HID];
__device__ uint16_t g_hoH16 [MTOK * HID],     g_hoL16 [MTOK * HID];
__device__ uint16_t g_pH16  [MTOK * HID],     g_pL16  [MTOK * HID];
__device__ uint16_t g_f1t16 [4 * HID * HID];
__device__ uint16_t g_f2t16 [4 * HID * HID];
__device__ uint16_t g_pjt16 [HID * HID];
__device__ uint16_t g_owt16 [(size_t)VV * HID];

// ============= transpose + bf16 split: in[K,N] f32 -> out[N,K] hi/lo ========
__global__ void tsplit(const float* __restrict__ in, __nv_bfloat16* __restrict__ oh,
                       __nv_bfloat16* __restrict__ ol, int K, int N,
                       long inZ, long outZrow)
{
    __shared__ float s[64][33];
    int k0 = blockIdx.x * 64, n0 = blockIdx.y * 32, z = blockIdx.z;
    in += (size_t)z * inZ;
    size_t rbase = (size_t)z * outZrow + n0;
    int tx = threadIdx.x, ty = threadIdx.y;       // 32 x 8
    #pragma unroll
    for (int i = 0; i < 8; i++)
        s[ty + 8 * i][tx] = in[(size_t)(k0 + ty + 8 * i) * N + n0 + tx];
    __syncthreads();
    int tid = ty * 32 + tx;
    #pragma unroll
    for (int j = 0; j < 4; j++) {
        int id = tid + 256 * j;                   // 0..1023
        int n = id >> 5, kp = id & 31;            // n row, k-pair
        float v0 = s[2 * kp][n], v1 = s[2 * kp + 1][n];
        __nv_bfloat16 h0 = __float2bfloat16(v0), h1 = __float2bfloat16(v1);
        __nv_bfloat162 hv; hv.x = h0; hv.y = h1;
        __nv_bfloat162 lv;
        lv.x = __float2bfloat16(v0 - __bfloat162float(h0));
        lv.y = __float2bfloat16(v1 - __bfloat162float(h1));
        size_t o = (rbase + n) * (size_t)K + k0 + 2 * kp;
        *reinterpret_cast<__nv_bfloat162*>(oh + o) = hv;
        *reinterpret_cast<__nv_bfloat162*>(ol + o) = lv;
    }
}

// ============= transpose to plain fp16: in[K,N] f32 -> out[N,K] =============
__global__ void tsplit16(const float* __restrict__ in, uint16_t* __restrict__ oh,
                         int K, int N)
{
    __shared__ float s[64][33];
    int k0 = blockIdx.x * 64, n0 = blockIdx.y * 32;
    int tx = threadIdx.x, ty = threadIdx.y;       // 32 x 8
    #pragma unroll
    for (int i = 0; i < 8; i++)
        s[ty + 8 * i][tx] = in[(size_t)(k0 + ty + 8 * i) * N + n0 + tx];
    __syncthreads();
    int tid = ty * 32 + tx;
    #pragma unroll
    for (int j = 0; j < 4; j++) {
        int id = tid + 256 * j;                   // 0..1023
        int n = id >> 5, kp = id & 31;
        __half h0 = __float2half_rn(s[2 * kp][n]);
        __half h1 = __float2half_rn(s[2 * kp + 1][n]);
        uint32_t pk = ((uint32_t)__half_as_ushort(h1) << 16) | __half_as_ushort(h0);
        size_t o = ((size_t)n0 + n) * (size_t)K + k0 + 2 * kp;
        *reinterpret_cast<uint32_t*>(oh + o) = pk;
    }
}

__global__ void pack_b3k(const float* __restrict__ ba, const float* __restrict__ bb,
                         const float* __restrict__ bo)
{
    int j = blockIdx.x * 256 + threadIdx.x;
    g_b3[j] = ba[j]; g_b3[1024 + j] = bb[j]; g_b3[2048 + j] = bo[j];
}

// ============= embedding gather + bf16 split ================================
__global__ void gather_emb(const int* __restrict__ x, const float* __restrict__ embed)
{
    int i = blockIdx.x * blockDim.x + threadIdx.x;   // over MTOK*256 float4s
    int t = i >> 8, c4 = i & 255;
    int tok = x[t];
    float4 v = reinterpret_cast<const float4*>(embed + (size_t)tok * EE)[c4];
    size_t o = (size_t)t * EE + c4 * 4;
    float vv[4] = {v.x, v.y, v.z, v.w};
    #pragma unroll
    for (int j = 0; j < 4; j++) {
        __nv_bfloat16 h = __float2bfloat16(vv[j]);
        g_embH[o + j] = h;
        g_embL[o + j] = __float2bfloat16(vv[j] - __bfloat162float(h));
    }
}

// ===================== split HMMA GEMM ======================================
// MODE 0 (bf16, 3 products): D = Ahi@Bhi^T + Ahi@Blo^T + Alo@Bhi^T
// MODE 1 (fp16, 2 products): D = Ahi@B^T + Alo@B^T  (B unsplit fp16)
// A*[M,K], B*[N,K] row-major 16-bit. Epilogue: +bias, act(0/1 tanh<1024/2 gelu),
// +res fp32, writes outF fp32 and/or outHi/outLo (MODE-typed split).
// Block 128x128, K-chunk 64, 3-stage cp.async pipeline.
template<int MODE>
__global__ void __launch_bounds__(256)
gemm_tc(const uint16_t* __restrict__ Ahi, const uint16_t* __restrict__ Alo,
        const uint16_t* __restrict__ Bhi, const uint16_t* __restrict__ Blo,
        const float* __restrict__ bias, const float* __restrict__ res,
        float* __restrict__ outF, uint16_t* __restrict__ outHi,
        uint16_t* __restrict__ outLo, int N, int K, int act)
{
    constexpr int STAGE = (MODE == 0) ? 65536 : 49152;
    extern __shared__ char smem[];
    const int tid = threadIdx.x;
    const int wid = tid >> 5, lane = tid & 31;
    const int m0 = blockIdx.x * 128, n0 = blockIdx.y * 128;
    const int wm = (wid & 1) * 64, wn = (wid >> 1) * 32;
    const uint32_t sb = smem_u32(smem);

    float acc[4][4][4];
    #pragma unroll
    for (int mi = 0; mi < 4; mi++)
        #pragma unroll
        for (int ni = 0; ni < 4; ni++)
            #pragma unroll
            for (int e = 0; e < 4; e++) acc[mi][ni][e] = 0.f;

    auto load_chunk = [&](uint32_t sdst, int k0) {
        #pragma unroll
        for (int t = 0; t < 4; t++) {
            int idx = tid + t * 256;               // 0..1023 16B lines per tile
            int r = idx >> 3, c8 = idx & 7;
            uint32_t off = SMEM_SWIZZLE_128B(r * 128 + c8 * 16);
            CP_ASYNC16(sdst + off,         Ahi + (size_t)(m0 + r) * K + k0 + c8 * 8);
            CP_ASYNC16(sdst + 16384 + off, Alo + (size_t)(m0 + r) * K + k0 + c8 * 8);
            CP_ASYNC16(sdst + 32768 + off, Bhi + (size_t)(n0 + r) * K + k0 + c8 * 8);
            if constexpr (MODE == 0)
                CP_ASYNC16(sdst + 49152 + off, Blo + (size_t)(n0 + r) * K + k0 + c8 * 8);
        }
    };

    const int nch = K / 64;
    load_chunk(sb, 0);
    CP_COMMIT();
    load_chunk(sb + STAGE, 64);
    CP_COMMIT();

    int stage = 0;
    for (int it = 0; it < nch; it++) {
        if (it + 1 < nch) { CP_WAIT1(); } else { CP_WAIT0(); }
        __syncthreads();
        if (it + 2 < nch) {
            int s2 = stage + 2; if (s2 >= 3) s2 -= 3;
            load_chunk(sb + s2 * STAGE, (it + 2) * 64);
            CP_COMMIT();
        }

        const uint32_t st = sb + stage * STAGE;
        const uint32_t tA1 = st, tA2 = st + 16384, tB1 = st + 32768, tB2 = st + 49152;
        const int lr = lane & 15, lg = (lane >> 4) << 4;

        #pragma unroll
        for (int kk = 0; kk < 4; kk++) {
            uint32_t a1[4][4], a2[4][4], b1[2][4], b2[2][4];
            #pragma unroll
            for (int mi = 0; mi < 4; mi++) {
                uint32_t off = SMEM_SWIZZLE_128B((wm + mi * 16 + lr) * 128 + kk * 32 + lg);
                LDSM_X4(a1[mi], tA1 + off);
                LDSM_X4(a2[mi], tA2 + off);
            }
            #pragma unroll
            for (int pi = 0; pi < 2; pi++) {
                uint32_t off = SMEM_SWIZZLE_128B((wn + pi * 16 + lr) * 128 + kk * 32 + lg);
                LDSM_X4(b1[pi], tB1 + off);
                if constexpr (MODE == 0) LDSM_X4(b2[pi], tB2 + off);
            }
            #pragma unroll
            for (int mi = 0; mi < 4; mi++) {
                #pragma unroll
                for (int pi = 0; pi < 2; pi++) {
                    if constexpr (MODE == 0) {
                        MMA_BF16(acc[mi][2 * pi],     a1[mi], b1[pi][0], b1[pi][2]);
                        MMA_BF16(acc[mi][2 * pi + 1], a1[mi], b1[pi][1], b1[pi][3]);
                        MMA_BF16(acc[mi][2 * pi],     a1[mi], b2[pi][0], b2[pi][2]);
                        MMA_BF16(acc[mi][2 * pi + 1], a1[mi], b2[pi][1], b2[pi][3]);
                        MMA_BF16(acc[mi][2 * pi],     a2[mi], b1[pi][0], b1[pi][2]);
                        MMA_BF16(acc[mi][2 * pi + 1], a2[mi], b1[pi][1], b1[pi][3]);
                    } else {
                        MMA_F16(acc[mi][2 * pi],     a1[mi], b1[pi][0], b1[pi][2]);
                        MMA_F16(acc[mi][2 * pi + 1], a1[mi], b1[pi][1], b1[pi][3]);
                        MMA_F16(acc[mi][2 * pi],     a2[mi], b1[pi][0], b1[pi][2]);
                        MMA_F16(acc[mi][2 * pi + 1], a2[mi], b1[pi][1], b1[pi][3]);
                    }
                }
            }
        }
        if (++stage == 3) stage = 0;
    }
    __syncthreads();

    // ---- epilogue: single pass through [128][132] fp32 smem tile ----
    float* ep = reinterpret_cast<float*>(smem);
    #pragma unroll
    for (int mi = 0; mi < 4; mi++) {
        int r0 = wm + mi * 16 + (lane >> 2);
        #pragma unroll
        for (int ni = 0; ni < 4; ni++) {
            int c = wn + ni * 8 + 2 * (lane & 3);
            ep[r0 * 132 + c]           = acc[mi][ni][0];
            ep[r0 * 132 + c + 1]       = acc[mi][ni][1];
            ep[(r0 + 8) * 132 + c]     = acc[mi][ni][2];
            ep[(r0 + 8) * 132 + c + 1] = acc[mi][ni][3];
        }
    }
    __syncthreads();
    #pragma unroll
    for (int i = 0; i < 16; i++) {
        int idx = tid + i * 256;                 // 0..4095 float4s
        int r = idx >> 5, c4 = idx & 31;
        int gc = n0 + c4 * 4;
        float4 v = *reinterpret_cast<float4*>(&ep[r * 132 + c4 * 4]);
        float4 b4 = *reinterpret_cast<const float4*>(bias + gc);
        float vv[4] = {v.x + b4.x, v.y + b4.y, v.z + b4.z, v.w + b4.w};
        if (act == 1) {
            #pragma unroll
            for (int j = 0; j < 4; j++)
                if (gc + j < 1024) vv[j] = tanhf(vv[j]);
        } else if (act == 2) {
            #pragma unroll
            for (int j = 0; j < 4; j++)
                vv[j] = 0.5f * vv[j] * (1.f + erff(vv[j] * 0.70710678118654752f));
        }
        size_t o = (size_t)(m0 + r) * N + gc;
        if (res) {
            float4 r4 = *reinterpret_cast<const float4*>(res + o);
            vv[0] += r4.x; vv[1] += r4.y; vv[2] += r4.z; vv[3] += r4.w;
        }
        if (outF) {
            float4 w = {vv[0], vv[1], vv[2], vv[3]};
            *reinterpret_cast<float4*>(outF + o) = w;
        }
        if (outHi) {
            #pragma unroll
            for (int j = 0; j < 4; j++) {
                if constexpr (MODE == 0) {
                    __nv_bfloat16 h = __float2bfloat16(vv[j]);
                    __nv_bfloat16 l = __float2bfloat16(vv[j] - __bfloat162float(h));
                    outHi[o + j] = __bfloat16_as_ushort(h);
                    outLo[o + j] = __bfloat16_as_ushort(l);
                } else {
                    __half h = __float2half_rn(vv[j]);
                    __half l = __float2half_rn(vv[j] - __half2float(h));
                    outHi[o + j] = __half_as_ushort(h);
                    outLo[o + j] = __half_as_ushort(l);
                }
            }
        }
    }
}

// ============= recurrence: 3-phase chunked affine scan ======================
__global__ void scan1()
{
    int c = blockIdx.x;
    int q = blockIdx.y * 256 + threadIdx.x;
    int b = q >> 10, jj = q & 1023;
    const float* base = g_abw + (size_t)b * LL * 3072 + jj;
    int l0 = c * 32;
    float A = 1.f, C = 0.f;
    #pragma unroll 8
    for (int i = 0; i < 32; i++) {
        float a  = base[(size_t)(l0 + i) * 3072];
        float bv = base[(size_t)(l0 + i) * 3072 + 1024];
        C = fmaf(a, C, bv * bv);
        A *= a;
    }
    g_scanA[c * MTOK + q] = A;
    g_scanC[c * MTOK + q] = C;
}

__global__ void scan2()
{
    int q = blockIdx.x * 256 + threadIdx.x;
    float h = 0.f;
    #pragma unroll
    for (int c = 0; c < 32; c++) {
        g_hst[c * MTOK + q] = h;
        h = fmaf(g_scanA[c * MTOK + q], h, g_scanC[c * MTOK + q]);
    }
}

__global__ void scan3()
{
    int c = blockIdx.x;
    int q = blockIdx.y * 256 + threadIdx.x;
    int b = q >> 10, jj = q & 1023;
    const float* base = g_abw + (size_t)b * LL * 3072 + jj;
    float* hsp = g_hs + b * HID + jj;
    float h = g_hst[c * MTOK + q];
    int l0 = c * 32;
    #pragma unroll 8
    for (int i = 0; i < 32; i++) {
        int l = l0 + i;
        float a  = base[(size_t)l * 3072];
        float bv = base[(size_t)l * 3072 + 1024];
        h = fmaf(a, h, bv * bv);
        hsp[(size_t)l * (BB * HID)] = h;
    }
}

// ============= per-head C projection + gating ===============================
__global__ void __launch_bounds__(256)
headmm(const float* __restrict__ Cw, const float* __restrict__ Cb)
{
    __shared__ float S [64][65];
    __shared__ float Cs[64][65];
    int tile = blockIdx.x, h = blockIdx.y;
    int t0 = tile * 64;
    int b = t0 >> 10, l0 = t0 & 1023;
    int tid = threadIdx.x;

    for (int i = tid; i < 64 * 64; i += 256) {
        int r = i >> 6, c = i & 63;
        S [r][c] = g_hs[(size_t)(l0 + r) * (BB * HID) + b * HID + h * 64 + c];
        Cs[r][c] = Cw[(size_t)h * 4096 + i];
    }
    __syncthreads();

    int ty = tid >> 4, tx = tid & 15;
    float acc[4][4] = {};
    for (int k = 0; k < 64; k++) {
        float ra[4], rb[4];
        #pragma unroll
        for (int i = 0; i < 4; i++) ra[i] = S[ty * 4 + i][k];
        #pragma unroll
        for (int j = 0; j < 4; j++) rb[j] = Cs[k][tx * 4 + j];
        #pragma unroll
        for (int i = 0; i < 4; i++)
            #pragma unroll
            for (int j = 0; j < 4; j++)
                acc[i][j] = fmaf(ra[i], rb[j], acc[i][j]);
    }

    #pragma unroll
    for (int i = 0; i < 4; i++) {
        int t = t0 + ty * 4 + i;
        #pragma unroll
        for (int j = 0; j < 4; j++) {
            int col = h * 64 + tx * 4 + j;
            float v = acc[i][j] + Cb[col];
            v *= g_abw[(size_t)t * 3072 + 2048 + col];
            g_z[(size_t)t * HID + col] = v;
        }
    }
}

// ============= u = z + LN(z), plus fp16 split of u ==========================
__device__ __forceinline__ float warpsum(float v)
{
    #pragma unroll
    for (int o = 16; o; o >>= 1) v += __shfl_xor_sync(0xffffffffu, v, o);
    return v;
}

__global__ void __launch_bounds__(256)
ln_resid(const float* __restrict__ gamma, const float* __restrict__ beta)
{
    int t = blockIdx.x;
    int tid = threadIdx.x;
    const float* z = g_z + (size_t)t * HID;
    float xv[4];
    float s = 0.f, s2 = 0.f;
    #pragma unroll
    for (int k = 0; k < 4; k++) {
        float v = z[tid + 256 * k];
        xv[k] = v; s += v; s2 += v * v;
    }
    __shared__ float sh[2][8];
    s = warpsum(s); s2 = warpsum(s2);
    int w = tid >> 5, ln = tid & 31;
    if (!ln) { sh[0][w] = s; sh[1][w] = s2; }
    __syncthreads();
    if (tid < 32) {
        float a  = (ln < 8) ? sh[0][ln] : 0.f;
        float b2 = (ln < 8) ? sh[1][ln] : 0.f;
        a = warpsum(a); b2 = warpsum(b2);
        if (!ln) { sh[0][0] = a; sh[1][0] = b2; }
    }
    __syncthreads();
    float mu   = sh[0][0] * (1.f / 1024.f);
    float var  = sh[1][0] * (1.f / 1024.f) - mu * mu;
    float rstd = rsqrtf(var + 1e-5f);
    float* u = g_u + (size_t)t * HID;
    #pragma unroll
    for (int k = 0; k < 4; k++) {
        int c = tid + 256 * k;
        float v = xv[k];
        float uu = v + (v - mu) * rstd * gamma[c] + beta[c];
        u[c] = uu;
        __half h = __float2half_rn(uu);
        g_uH16[(size_t)t * HID + c] = __half_as_ushort(h);
        g_uL16[(size_t)t * HID + c] =
            __half_as_ushort(__float2half_rn(uu - __half2float(h)));
    }
}

// ===================== launch ===============================================
extern "C" void kernel_launch(void* const* d_in, const int* in_sizes, int n_in,
                              void* d_out, int out_size)
{
    const int*   x      = (const int*)  d_in[0];
    const float* embed  = (const float*)d_in[1];
    const float* Wa     = (const float*)d_in[2];
    const float* ba     = (const float*)d_in[3];
    const float* Wb     = (const float*)d_in[4];
    const float* bb     = (const float*)d_in[5];
    const float* Wo     = (const float*)d_in[6];
    const float* bo     = (const float*)d_in[7];
    const float* Cw     = (const float*)d_in[8];
    const float* Cb     = (const float*)d_in[9];
    const float* proj_w = (const float*)d_in[10];
    const float* proj_b = (const float*)d_in[11];
    const float* gamma  = (const float*)d_in[12];
    const float* beta   = (const float*)d_in[13];
    const float* ffn1_w = (const float*)d_in[14];
    const float* ffn1_b = (const float*)d_in[15];
    const float* ffn2_w = (const float*)d_in[16];
    const float* ffn2_b = (const float*)d_in[17];
    const float* out_w  = (const float*)d_in[18];
    const float* out_b  = (const float*)d_in[19];
    float* out = (float*)d_out;
    (void)in_sizes; (void)n_in; (void)out_size;

    cudaFuncSetAttribute(gemm_tc<0>, cudaFuncAttributeMaxDynamicSharedMemorySize, 3 * 65536);
    cudaFuncSetAttribute(gemm_tc<1>, cudaFuncAttributeMaxDynamicSharedMemorySize, 3 * 49152);

    float *abw, *uf, *b3p;
    __nv_bfloat16 *embH, *embL, *W3tH, *W3tL;
    uint16_t *uH16, *uL16, *midH16, *midL16, *hoH16, *hoL16, *pH16, *pL16;
    uint16_t *f1t16, *f2t16, *pjt16, *owt16;
    cudaGetSymbolAddress((void**)&abw,    g_abw);
    cudaGetSymbolAddress((void**)&uf,     g_u);
    cudaGetSymbolAddress((void**)&b3p,    g_b3);
    cudaGetSymbolAddress((void**)&embH,   g_embH);   cudaGetSymbolAddress((void**)&embL,   g_embL);
    cudaGetSymbolAddress((void**)&W3tH,   g_W3tH);   cudaGetSymbolAddress((void**)&W3tL,   g_W3tL);
    cudaGetSymbolAddress((void**)&uH16,   g_uH16);   cudaGetSymbolAddress((void**)&uL16,   g_uL16);
    cudaGetSymbolAddress((void**)&midH16, g_midH16); cudaGetSymbolAddress((void**)&midL16, g_midL16);
    cudaGetSymbolAddress((void**)&hoH16,  g_hoH16);  cudaGetSymbolAddress((void**)&hoL16,  g_hoL16);
    cudaGetSymbolAddress((void**)&pH16,   g_pH16);   cudaGetSymbolAddress((void**)&pL16,   g_pL16);
    cudaGetSymbolAddress((void**)&f1t16,  g_f1t16);
    cudaGetSymbolAddress((void**)&f2t16,  g_f2t16);
    cudaGetSymbolAddress((void**)&pjt16,  g_pjt16);
    cudaGetSymbolAddress((void**)&owt16,  g_owt16);

    dim3 tb(32, 8);
    // W3 (abw path): bf16 hi/lo split, transposed
    tsplit<<<dim3(16, 2, 16), tb>>>(Wa, W3tH,               W3tL,               1024, 64, (long)EE * DD, 64);
    tsplit<<<dim3(16, 2, 16), tb>>>(Wb, W3tH + 1024 * 1024, W3tL + 1024 * 1024, 1024, 64, (long)EE * DD, 64);
    tsplit<<<dim3(16, 2, 16), tb>>>(Wo, W3tH + 2048 * 1024, W3tL + 2048 * 1024, 1024, 64, (long)EE * DD, 64);
    // FFN/proj/out weights: plain fp16, transposed
    tsplit16<<<dim3(16, 128, 1), tb>>>(ffn1_w, f1t16, 1024, 4096);
    tsplit16<<<dim3(64, 32, 1),  tb>>>(ffn2_w, f2t16, 4096, 1024);
    tsplit16<<<dim3(16, 32, 1),  tb>>>(proj_w, pjt16, 1024, 1024);
    tsplit16<<<dim3(16, 1000, 1), tb>>>(out_w, owt16, 1024, VV);
    pack_b3k<<<4, 256>>>(ba, bb, bo);

    // embedding gather + bf16 split
    gather_emb<<<(MTOK * 256) / 256, 256>>>(x, embed);

    // abw = [tanh(emb@Wa+ba) | emb@Wb+bb | emb@Wo+bo]  (bf16 3-prod, fp32 out)
    gemm_tc<0><<<dim3(16, 24), 256, 3 * 65536>>>(
        (const uint16_t*)embH, (const uint16_t*)embL,
        (const uint16_t*)W3tH, (const uint16_t*)W3tL,
        b3p, nullptr, abw, nullptr, nullptr, 3072, 1024, 1);
    // recurrence
    scan1<<<dim3(32, 8), 256>>>();
    scan2<<<8, 256>>>();
    scan3<<<dim3(32, 8), 256>>>();
    // per-head C projection + gating
    headmm<<<dim3(MTOK / 64, HH), 256>>>(Cw, Cb);
    // u = z + LN(z), fp16 split
    ln_resid<<<MTOK, 256>>>(gamma, beta);
    // FFN1 + gelu -> mid (fp16 2-prod, fp16 split out)
    gemm_tc<1><<<dim3(16, 32), 256, 3 * 49152>>>(
        uH16, uL16, f1t16, nullptr, ffn1_b,
        nullptr, nullptr, midH16, midL16, 4096, 1024, 2);
    // FFN2 + residual u -> hout
    gemm_tc<1><<<dim3(16, 8), 256, 3 * 49152>>>(
        midH16, midL16, f2t16, nullptr, ffn2_b,
        uf, nullptr, hoH16, hoL16, 1024, 4096, 0);
    // proj -> p
    gemm_tc<1><<<dim3(16, 8), 256, 3 * 49152>>>(
        hoH16, hoL16, pjt16, nullptr, proj_b,
        nullptr, nullptr, pH16, pL16, 1024, 1024, 0);
    // logits (fp32 out)
    gemm_tc<1><<<dim3(16, 250), 256, 3 * 49152>>>(
        pH16, pL16, owt16, nullptr, out_b,
        nullptr, out, nullptr, nullptr, VV, 1024, 0);
}

// round 14
// speedup vs baseline: 5.8248x; 1.4847x over previous
#include <cuda_runtime.h>
#include <cuda_bf16.h>
#include <cuda_fp16.h>
#include <math.h>
#include <stdint.h>

// Problem constants
#define BB   2
#define LL   1024
#define VV   32000
#define EE   1024
#define HH   16
#define DD   64
#define HID  1024
#define MTOK (BB*LL)      // 2048 tokens

// ===================== helpers (plain sm_80+ PTX only) ======================
__device__ __forceinline__ uint32_t smem_u32(const void* p) {
    uint32_t a;
    asm("{ .reg .u64 t; cvta.to.shared.u64 t, %1; cvt.u32.u64 %0, t; }"
        : "=r"(a) : "l"(p));
    return a;
}
#define SMEM_SWIZZLE_128B(o) ((o) ^ (((o) >> 3) & 0x70))

#define CP_ASYNC16(dst, src) \
    asm volatile("cp.async.cg.shared.global [%0], [%1], 16;" \
                 :: "r"(dst), "l"(src) : "memory")
#define CP_COMMIT() asm volatile("cp.async.commit_group;" ::: "memory")
#define CP_WAIT1()  asm volatile("cp.async.wait_group 1;" ::: "memory")
#define CP_WAIT0()  asm volatile("cp.async.wait_group 0;" ::: "memory")

#define LDSM_X4(d, addr) \
    asm volatile("ldmatrix.sync.aligned.m8n8.x4.shared.b16 {%0,%1,%2,%3}, [%4];" \
                 : "=r"((d)[0]), "=r"((d)[1]), "=r"((d)[2]), "=r"((d)[3]) : "r"(addr))

#define MMA_BF16(c, a, b0_, b1_) \
    asm volatile("mma.sync.aligned.m16n8k16.row.col.f32.bf16.bf16.f32 " \
                 "{%0,%1,%2,%3}, {%4,%5,%6,%7}, {%8,%9}, {%0,%1,%2,%3};" \
                 : "+f"((c)[0]), "+f"((c)[1]), "+f"((c)[2]), "+f"((c)[3]) \
                 : "r"((a)[0]), "r"((a)[1]), "r"((a)[2]), "r"((a)[3]), \
                   "r"(b0_), "r"(b1_))

#define MMA_F16(c, a, b0_, b1_) \
    asm volatile("mma.sync.aligned.m16n8k16.row.col.f32.f16.f16.f32 " \
                 "{%0,%1,%2,%3}, {%4,%5,%6,%7}, {%8,%9}, {%0,%1,%2,%3};" \
                 : "+f"((c)[0]), "+f"((c)[1]), "+f"((c)[2]), "+f"((c)[3]) \
                 : "r"((a)[0]), "r"((a)[1]), "r"((a)[2]), "r"((a)[3]), \
                   "r"(b0_), "r"(b1_))

// ===================== scratch (device globals; no allocation) ==============
__device__ float g_abw  [MTOK * 3 * HID];
__device__ float g_hs   [MTOK * HID];
__device__ float g_z    [MTOK * HID];
__device__ float g_u    [MTOK * HID];
__device__ float g_b3   [3 * HID];
__device__ float g_scanA[32 * MTOK];
__device__ float g_scanC[32 * MTOK];
__device__ float g_hst  [32 * MTOK];

// bf16 split (abw path only)
__device__ __nv_bfloat16 g_embH [MTOK * EE],    g_embL [MTOK * EE];
__device__ __nv_bfloat16 g_W3tH [3 * HID * EE], g_W3tL [3 * HID * EE];
// fp16 split activations (hi/lo) and unsplit fp16 weights
__device__ uint16_t g_uH16  [MTOK * HID],     g_uL16  [MTOK * HID];
__device__ uint16_t g_midH16[MTOK * 4 * HID], g_midL16[MTOK * 4 * HID];
__device__ uint16_t g_hoH16 [MTOK * HID],     g_hoL16 [MTOK * HID];
__device__ uint16_t g_pH16  [MTOK * HID],     g_pL16  [MTOK * HID];
__device__ uint16_t g_f1t16 [4 * HID * HID];
__device__ uint16_t g_f2t16 [4 * HID * HID];
__device__ uint16_t g_pjt16 [HID * HID];
__device__ uint16_t g_owt16 [(size_t)VV * HID];

// ============= transpose + bf16 split: in[K,N] f32 -> out[N,K] hi/lo ========
__global__ void tsplit(const float* __restrict__ in, __nv_bfloat16* __restrict__ oh,
                       __nv_bfloat16* __restrict__ ol, int K, int N,
                       long inZ, long outZrow)
{
    __shared__ float s[64][33];
    int k0 = blockIdx.x * 64, n0 = blockIdx.y * 32, z = blockIdx.z;
    in += (size_t)z * inZ;
    size_t rbase = (size_t)z * outZrow + n0;
    int tx = threadIdx.x, ty = threadIdx.y;       // 32 x 8
    #pragma unroll
    for (int i = 0; i < 8; i++)
        s[ty + 8 * i][tx] = in[(size_t)(k0 + ty + 8 * i) * N + n0 + tx];
    __syncthreads();
    int tid = ty * 32 + tx;
    #pragma unroll
    for (int j = 0; j < 4; j++) {
        int id = tid + 256 * j;                   // 0..1023
        int n = id >> 5, kp = id & 31;            // n row, k-pair
        float v0 = s[2 * kp][n], v1 = s[2 * kp + 1][n];
        __nv_bfloat16 h0 = __float2bfloat16(v0), h1 = __float2bfloat16(v1);
        __nv_bfloat162 hv; hv.x = h0; hv.y = h1;
        __nv_bfloat162 lv;
        lv.x = __float2bfloat16(v0 - __bfloat162float(h0));
        lv.y = __float2bfloat16(v1 - __bfloat162float(h1));
        size_t o = (rbase + n) * (size_t)K + k0 + 2 * kp;
        *reinterpret_cast<__nv_bfloat162*>(oh + o) = hv;
        *reinterpret_cast<__nv_bfloat162*>(ol + o) = lv;
    }
}

// ============= transpose to plain fp16: in[K,N] f32 -> out[N,K] =============
__global__ void tsplit16(const float* __restrict__ in, uint16_t* __restrict__ oh,
                         int K, int N)
{
    __shared__ float s[64][33];
    int k0 = blockIdx.x * 64, n0 = blockIdx.y * 32;
    int tx = threadIdx.x, ty = threadIdx.y;       // 32 x 8
    #pragma unroll
    for (int i = 0; i < 8; i++)
        s[ty + 8 * i][tx] = in[(size_t)(k0 + ty + 8 * i) * N + n0 + tx];
    __syncthreads();
    int tid = ty * 32 + tx;
    #pragma unroll
    for (int j = 0; j < 4; j++) {
        int id = tid + 256 * j;                   // 0..1023
        int n = id >> 5, kp = id & 31;
        __half h0 = __float2half_rn(s[2 * kp][n]);
        __half h1 = __float2half_rn(s[2 * kp + 1][n]);
        uint32_t pk = ((uint32_t)__half_as_ushort(h1) << 16) | __half_as_ushort(h0);
        size_t o = ((size_t)n0 + n) * (size_t)K + k0 + 2 * kp;
        *reinterpret_cast<uint32_t*>(oh + o) = pk;
    }
}

__global__ void pack_b3k(const float* __restrict__ ba, const float* __restrict__ bb,
                         const float* __restrict__ bo)
{
    int j = blockIdx.x * 256 + threadIdx.x;
    g_b3[j] = ba[j]; g_b3[1024 + j] = bb[j]; g_b3[2048 + j] = bo[j];
}

// ============= embedding gather + bf16 split ================================
__global__ void gather_emb(const int* __restrict__ x, const float* __restrict__ embed)
{
    int i = blockIdx.x * blockDim.x + threadIdx.x;   // over MTOK*256 float4s
    int t = i >> 8, c4 = i & 255;
    int tok = x[t];
    float4 v = reinterpret_cast<const float4*>(embed + (size_t)tok * EE)[c4];
    size_t o = (size_t)t * EE + c4 * 4;
    float vv[4] = {v.x, v.y, v.z, v.w};
    #pragma unroll
    for (int j = 0; j < 4; j++) {
        __nv_bfloat16 h = __float2bfloat16(vv[j]);
        g_embH[o + j] = h;
        g_embL[o + j] = __float2bfloat16(vv[j] - __bfloat162float(h));
    }
}

// ===================== split HMMA GEMM ======================================
// MODE 0 (bf16, 3 products): D = Ahi@Bhi^T + Ahi@Blo^T + Alo@Bhi^T
// MODE 1 (fp16, 2 products): D = Ahi@B^T + Alo@B^T  (B unsplit fp16)
// MODE 2 (fp16, 1 product):  D = Ahi@B^T            (A, B unsplit fp16)
// A*[M,K], B*[N,K] row-major 16-bit. Epilogue: +bias, act(0/1 tanh<1024/2 gelu),
// +res fp32, writes outF fp32 and/or outHi/outLo (MODE-typed split).
// Block 128x128, K-chunk 64, 3-stage cp.async pipeline.
template<int MODE>
__global__ void __launch_bounds__(256)
gemm_tc(const uint16_t* __restrict__ Ahi, const uint16_t* __restrict__ Alo,
        const uint16_t* __restrict__ Bhi, const uint16_t* __restrict__ Blo,
        const float* __restrict__ bias, const float* __restrict__ res,
        float* __restrict__ outF, uint16_t* __restrict__ outHi,
        uint16_t* __restrict__ outLo, int N, int K, int act)
{
    constexpr int STAGE = (MODE == 0) ? 65536 : (MODE == 1) ? 49152 : 32768;
    // tile offsets within a stage: A at 0, (Alo at 16K if MODE<2),
    // B at 16K(MODE2)/32K(else), Blo at 48K (MODE0)
    constexpr int AOFF2 = 16384;
    constexpr int BOFF  = (MODE == 2) ? 16384 : 32768;
    constexpr int BOFF2 = 49152;
    extern __shared__ char smem[];
    const int tid = threadIdx.x;
    const int wid = tid >> 5, lane = tid & 31;
    const int m0 = blockIdx.x * 128, n0 = blockIdx.y * 128;
    const int wm = (wid & 1) * 64, wn = (wid >> 1) * 32;
    const uint32_t sb = smem_u32(smem);

    float acc[4][4][4];
    #pragma unroll
    for (int mi = 0; mi < 4; mi++)
        #pragma unroll
        for (int ni = 0; ni < 4; ni++)
            #pragma unroll
            for (int e = 0; e < 4; e++) acc[mi][ni][e] = 0.f;

    auto load_chunk = [&](uint32_t sdst, int k0) {
        #pragma unroll
        for (int t = 0; t < 4; t++) {
            int idx = tid + t * 256;               // 0..1023 16B lines per tile
            int r = idx >> 3, c8 = idx & 7;
            uint32_t off = SMEM_SWIZZLE_128B(r * 128 + c8 * 16);
            CP_ASYNC16(sdst + off,        Ahi + (size_t)(m0 + r) * K + k0 + c8 * 8);
            if constexpr (MODE < 2)
                CP_ASYNC16(sdst + AOFF2 + off, Alo + (size_t)(m0 + r) * K + k0 + c8 * 8);
            CP_ASYNC16(sdst + BOFF + off, Bhi + (size_t)(n0 + r) * K + k0 + c8 * 8);
            if constexpr (MODE == 0)
                CP_ASYNC16(sdst + BOFF2 + off, Blo + (size_t)(n0 + r) * K + k0 + c8 * 8);
        }
    };

    const int nch = K / 64;
    load_chunk(sb, 0);
    CP_COMMIT();
    load_chunk(sb + STAGE, 64);
    CP_COMMIT();

    int stage = 0;
    for (int it = 0; it < nch; it++) {
        if (it + 1 < nch) { CP_WAIT1(); } else { CP_WAIT0(); }
        __syncthreads();
        if (it + 2 < nch) {
            int s2 = stage + 2; if (s2 >= 3) s2 -= 3;
            load_chunk(sb + s2 * STAGE, (it + 2) * 64);
            CP_COMMIT();
        }

        const uint32_t st = sb + stage * STAGE;
        const uint32_t tA1 = st, tA2 = st + AOFF2, tB1 = st + BOFF, tB2 = st + BOFF2;
        const int lr = lane & 15, lg = (lane >> 4) << 4;

        #pragma unroll
        for (int kk = 0; kk < 4; kk++) {
            uint32_t a1[4][4], a2[4][4], b1[2][4], b2[2][4];
            #pragma unroll
            for (int mi = 0; mi < 4; mi++) {
                uint32_t off = SMEM_SWIZZLE_128B((wm + mi * 16 + lr) * 128 + kk * 32 + lg);
                LDSM_X4(a1[mi], tA1 + off);
                if constexpr (MODE < 2) LDSM_X4(a2[mi], tA2 + off);
            }
            #pragma unroll
            for (int pi = 0; pi < 2; pi++) {
                uint32_t off = SMEM_SWIZZLE_128B((wn + pi * 16 + lr) * 128 + kk * 32 + lg);
                LDSM_X4(b1[pi], tB1 + off);
                if constexpr (MODE == 0) LDSM_X4(b2[pi], tB2 + off);
            }
            #pragma unroll
            for (int mi = 0; mi < 4; mi++) {
                #pragma unroll
                for (int pi = 0; pi < 2; pi++) {
                    if constexpr (MODE == 0) {
                        MMA_BF16(acc[mi][2 * pi],     a1[mi], b1[pi][0], b1[pi][2]);
                        MMA_BF16(acc[mi][2 * pi + 1], a1[mi], b1[pi][1], b1[pi][3]);
                        MMA_BF16(acc[mi][2 * pi],     a1[mi], b2[pi][0], b2[pi][2]);
                        MMA_BF16(acc[mi][2 * pi + 1], a1[mi], b2[pi][1], b2[pi][3]);
                        MMA_BF16(acc[mi][2 * pi],     a2[mi], b1[pi][0], b1[pi][2]);
                        MMA_BF16(acc[mi][2 * pi + 1], a2[mi], b1[pi][1], b1[pi][3]);
                    } else if constexpr (MODE == 1) {
                        MMA_F16(acc[mi][2 * pi],     a1[mi], b1[pi][0], b1[pi][2]);
                        MMA_F16(acc[mi][2 * pi + 1], a1[mi], b1[pi][1], b1[pi][3]);
                        MMA_F16(acc[mi][2 * pi],     a2[mi], b1[pi][0], b1[pi][2]);
                        MMA_F16(acc[mi][2 * pi + 1], a2[mi], b1[pi][1], b1[pi][3]);
                    } else {
                        MMA_F16(acc[mi][2 * pi],     a1[mi], b1[pi][0], b1[pi][2]);
                        MMA_F16(acc[mi][2 * pi + 1], a1[mi], b1[pi][1], b1[pi][3]);
                    }
                }
            }
        }
        if (++stage == 3) stage = 0;
    }
    __syncthreads();

    // ---- epilogue: single pass through [128][132] fp32 smem tile ----
    float* ep = reinterpret_cast<float*>(smem);
    #pragma unroll
    for (int mi = 0; mi < 4; mi++) {
        int r0 = wm + mi * 16 + (lane >> 2);
        #pragma unroll
        for (int ni = 0; ni < 4; ni++) {
            int c = wn + ni * 8 + 2 * (lane & 3);
            ep[r0 * 132 + c]           = acc[mi][ni][0];
            ep[r0 * 132 + c + 1]       = acc[mi][ni][1];
            ep[(r0 + 8) * 132 + c]     = acc[mi][ni][2];
            ep[(r0 + 8) * 132 + c + 1] = acc[mi][ni][3];
        }
    }
    __syncthreads();
    #pragma unroll
    for (int i = 0; i < 16; i++) {
        int idx = tid + i * 256;                 // 0..4095 float4s
        int r = idx >> 5, c4 = idx & 31;
        int gc = n0 + c4 * 4;
        float4 v = *reinterpret_cast<float4*>(&ep[r * 132 + c4 * 4]);
        float4 b4 = *reinterpret_cast<const float4*>(bias + gc);
        float vv[4] = {v.x + b4.x, v.y + b4.y, v.z + b4.z, v.w + b4.w};
        if (act == 1) {
            #pragma unroll
            for (int j = 0; j < 4; j++)
                if (gc + j < 1024) vv[j] = tanhf(vv[j]);
        } else if (act == 2) {
            #pragma unroll
            for (int j = 0; j < 4; j++)
                vv[j] = 0.5f * vv[j] * (1.f + erff(vv[j] * 0.70710678118654752f));
        }
        size_t o = (size_t)(m0 + r) * N + gc;
        if (res) {
            float4 r4 = *reinterpret_cast<const float4*>(res + o);
            vv[0] += r4.x; vv[1] += r4.y; vv[2] += r4.z; vv[3] += r4.w;
        }
        if (outF) {
            float4 w = {vv[0], vv[1], vv[2], vv[3]};
            *reinterpret_cast<float4*>(outF + o) = w;
        }
        if (outHi) {
            #pragma unroll
            for (int j = 0; j < 4; j++) {
                if constexpr (MODE == 0) {
                    __nv_bfloat16 h = __float2bfloat16(vv[j]);
                    __nv_bfloat16 l = __float2bfloat16(vv[j] - __bfloat162float(h));
                    outHi[o + j] = __bfloat16_as_ushort(h);
                    outLo[o + j] = __bfloat16_as_ushort(l);
                } else {
                    __half h = __float2half_rn(vv[j]);
                    __half l = __float2half_rn(vv[j] - __half2float(h));
                    outHi[o + j] = __half_as_ushort(h);
                    outLo[o + j] = __half_as_ushort(l);
                }
            }
        }
    }
}

// ============= recurrence: 3-phase chunked affine scan ======================
__global__ void scan1()
{
    int c = blockIdx.x;
    int q = blockIdx.y * 256 + threadIdx.x;
    int b = q >> 10, jj = q & 1023;
    const float* base = g_abw + (size_t)b * LL * 3072 + jj;
    int l0 = c * 32;
    float A = 1.f, C = 0.f;
    #pragma unroll 8
    for (int i = 0; i < 32; i++) {
        float a  = base[(size_t)(l0 + i) * 3072];
        float bv = base[(size_t)(l0 + i) * 3072 + 1024];
        C = fmaf(a, C, bv * bv);
        A *= a;
    }
    g_scanA[c * MTOK + q] = A;
    g_scanC[c * MTOK + q] = C;
}

__global__ void scan2()
{
    int q = blockIdx.x * 256 + threadIdx.x;
    float h = 0.f;
    #pragma unroll
    for (int c = 0; c < 32; c++) {
        g_hst[c * MTOK + q] = h;
        h = fmaf(g_scanA[c * MTOK + q], h, g_scanC[c * MTOK + q]);
    }
}

__global__ void scan3()
{
    int c = blockIdx.x;
    int q = blockIdx.y * 256 + threadIdx.x;
    int b = q >> 10, jj = q & 1023;
    const float* base = g_abw + (size_t)b * LL * 3072 + jj;
    float* hsp = g_hs + b * HID + jj;
    float h = g_hst[c * MTOK + q];
    int l0 = c * 32;
    #pragma unroll 8
    for (int i = 0; i < 32; i++) {
        int l = l0 + i;
        float a  = base[(size_t)l * 3072];
        float bv = base[(size_t)l * 3072 + 1024];
        h = fmaf(a, h, bv * bv);
        hsp[(size_t)l * (BB * HID)] = h;
    }
}

// ============= per-head C projection + gating ===============================
__global__ void __launch_bounds__(256)
headmm(const float* __restrict__ Cw, const float* __restrict__ Cb)
{
    __shared__ float S [64][65];
    __shared__ float Cs[64][65];
    int tile = blockIdx.x, h = blockIdx.y;
    int t0 = tile * 64;
    int b = t0 >> 10, l0 = t0 & 1023;
    int tid = threadIdx.x;

    for (int i = tid; i < 64 * 64; i += 256) {
        int r = i >> 6, c = i & 63;
        S [r][c] = g_hs[(size_t)(l0 + r) * (BB * HID) + b * HID + h * 64 + c];
        Cs[r][c] = Cw[(size_t)h * 4096 + i];
    }
    __syncthreads();

    int ty = tid >> 4, tx = tid & 15;
    float acc[4][4] = {};
    for (int k = 0; k < 64; k++) {
        float ra[4], rb[4];
        #pragma unroll
        for (int i = 0; i < 4; i++) ra[i] = S[ty * 4 + i][k];
        #pragma unroll
        for (int j = 0; j < 4; j++) rb[j] = Cs[k][tx * 4 + j];
        #pragma unroll
        for (int i = 0; i < 4; i++)
            #pragma unroll
            for (int j = 0; j < 4; j++)
                acc[i][j] = fmaf(ra[i], rb[j], acc[i][j]);
    }

    #pragma unroll
    for (int i = 0; i < 4; i++) {
        int t = t0 + ty * 4 + i;
        #pragma unroll
        for (int j = 0; j < 4; j++) {
            int col = h * 64 + tx * 4 + j;
            float v = acc[i][j] + Cb[col];
            v *= g_abw[(size_t)t * 3072 + 2048 + col];
            g_z[(size_t)t * HID + col] = v;
        }
    }
}

// ============= u = z + LN(z), plus fp16 split of u ==========================
__device__ __forceinline__ float warpsum(float v)
{
    #pragma unroll
    for (int o = 16; o; o >>= 1) v += __shfl_xor_sync(0xffffffffu, v, o);
    return v;
}

__global__ void __launch_bounds__(256)
ln_resid(const float* __restrict__ gamma, const float* __restrict__ beta)
{
    int t = blockIdx.x;
    int tid = threadIdx.x;
    const float* z = g_z + (size_t)t * HID;
    float xv[4];
    float s = 0.f, s2 = 0.f;
    #pragma unroll
    for (int k = 0; k < 4; k++) {
        float v = z[tid + 256 * k];
        xv[k] = v; s += v; s2 += v * v;
    }
    __shared__ float sh[2][8];
    s = warpsum(s); s2 = warpsum(s2);
    int w = tid >> 5, ln = tid & 31;
    if (!ln) { sh[0][w] = s; sh[1][w] = s2; }
    __syncthreads();
    if (tid < 32) {
        float a  = (ln < 8) ? sh[0][ln] : 0.f;
        float b2 = (ln < 8) ? sh[1][ln] : 0.f;
        a = warpsum(a); b2 = warpsum(b2);
        if (!ln) { sh[0][0] = a; sh[1][0] = b2; }
    }
    __syncthreads();
    float mu   = sh[0][0] * (1.f / 1024.f);
    float var  = sh[1][0] * (1.f / 1024.f) - mu * mu;
    float rstd = rsqrtf(var + 1e-5f);
    float* u = g_u + (size_t)t * HID;
    #pragma unroll
    for (int k = 0; k < 4; k++) {
        int c = tid + 256 * k;
        float v = xv[k];
        float uu = v + (v - mu) * rstd * gamma[c] + beta[c];
        u[c] = uu;
        __half h = __float2half_rn(uu);
        g_uH16[(size_t)t * HID + c] = __half_as_ushort(h);
        g_uL16[(size_t)t * HID + c] =
            __half_as_ushort(__float2half_rn(uu - __half2float(h)));
    }
}

// ===================== launch ===============================================
extern "C" void kernel_launch(void* const* d_in, const int* in_sizes, int n_in,
                              void* d_out, int out_size)
{
    const int*   x      = (const int*)  d_in[0];
    const float* embed  = (const float*)d_in[1];
    const float* Wa     = (const float*)d_in[2];
    const float* ba     = (const float*)d_in[3];
    const float* Wb     = (const float*)d_in[4];
    const float* bb     = (const float*)d_in[5];
    const float* Wo     = (const float*)d_in[6];
    const float* bo     = (const float*)d_in[7];
    const float* Cw     = (const float*)d_in[8];
    const float* Cb     = (const float*)d_in[9];
    const float* proj_w = (const float*)d_in[10];
    const float* proj_b = (const float*)d_in[11];
    const float* gamma  = (const float*)d_in[12];
    const float* beta   = (const float*)d_in[13];
    const float* ffn1_w = (const float*)d_in[14];
    const float* ffn1_b = (const float*)d_in[15];
    const float* ffn2_w = (const float*)d_in[16];
    const float* ffn2_b = (const float*)d_in[17];
    const float* out_w  = (const float*)d_in[18];
    const float* out_b  = (const float*)d_in[19];
    float* out = (float*)d_out;
    (void)in_sizes; (void)n_in; (void)out_size;

    cudaFuncSetAttribute(gemm_tc<0>, cudaFuncAttributeMaxDynamicSharedMemorySize, 3 * 65536);
    cudaFuncSetAttribute(gemm_tc<1>, cudaFuncAttributeMaxDynamicSharedMemorySize, 3 * 49152);
    cudaFuncSetAttribute(gemm_tc<2>, cudaFuncAttributeMaxDynamicSharedMemorySize, 3 * 32768);

    float *abw, *uf, *b3p;
    __nv_bfloat16 *embH, *embL, *W3tH, *W3tL;
    uint16_t *uH16, *uL16, *midH16, *midL16, *hoH16, *hoL16, *pH16, *pL16;
    uint16_t *f1t16, *f2t16, *pjt16, *owt16;
    cudaGetSymbolAddress((void**)&abw,    g_abw);
    cudaGetSymbolAddress((void**)&uf,     g_u);
    cudaGetSymbolAddress((void**)&b3p,    g_b3);
    cudaGetSymbolAddress((void**)&embH,   g_embH);   cudaGetSymbolAddress((void**)&embL,   g_embL);
    cudaGetSymbolAddress((void**)&W3tH,   g_W3tH);   cudaGetSymbolAddress((void**)&W3tL,   g_W3tL);
    cudaGetSymbolAddress((void**)&uH16,   g_uH16);   cudaGetSymbolAddress((void**)&uL16,   g_uL16);
    cudaGetSymbolAddress((void**)&midH16, g_midH16); cudaGetSymbolAddress((void**)&midL16, g_midL16);
    cudaGetSymbolAddress((void**)&hoH16,  g_hoH16);  cudaGetSymbolAddress((void**)&hoL16,  g_hoL16);
    cudaGetSymbolAddress((void**)&pH16,   g_pH16);   cudaGetSymbolAddress((void**)&pL16,   g_pL16);
    cudaGetSymbolAddress((void**)&f1t16,  g_f1t16);
    cudaGetSymbolAddress((void**)&f2t16,  g_f2t16);
    cudaGetSymbolAddress((void**)&pjt16,  g_pjt16);
    cudaGetSymbolAddress((void**)&owt16,  g_owt16);

    dim3 tb(32, 8);
    // W3 (abw path): bf16 hi/lo split, transposed
    tsplit<<<dim3(16, 2, 16), tb>>>(Wa, W3tH,               W3tL,               1024, 64, (long)EE * DD, 64);
    tsplit<<<dim3(16, 2, 16), tb>>>(Wb, W3tH + 1024 * 1024, W3tL + 1024 * 1024, 1024, 64, (long)EE * DD, 64);
    tsplit<<<dim3(16, 2, 16), tb>>>(Wo, W3tH + 2048 * 1024, W3tL + 2048 * 1024, 1024, 64, (long)EE * DD, 64);
    // FFN/proj/out weights: plain fp16, transposed
    tsplit16<<<dim3(16, 128, 1), tb>>>(ffn1_w, f1t16, 1024, 4096);
    tsplit16<<<dim3(64, 32, 1),  tb>>>(ffn2_w, f2t16, 4096, 1024);
    tsplit16<<<dim3(16, 32, 1),  tb>>>(proj_w, pjt16, 1024, 1024);
    tsplit16<<<dim3(16, 1000, 1), tb>>>(out_w, owt16, 1024, VV);
    pack_b3k<<<4, 256>>>(ba, bb, bo);

    // embedding gather + bf16 split
    gather_emb<<<(MTOK * 256) / 256, 256>>>(x, embed);

    // abw = [tanh(emb@Wa+ba) | emb@Wb+bb | emb@Wo+bo]  (bf16 3-prod, fp32 out)
    gemm_tc<0><<<dim3(16, 24), 256, 3 * 65536>>>(
        (const uint16_t*)embH, (const uint16_t*)embL,
        (const uint16_t*)W3tH, (const uint16_t*)W3tL,
        b3p, nullptr, abw, nullptr, nullptr, 3072, 1024, 1);
    // recurrence
    scan1<<<dim3(32, 8), 256>>>();
    scan2<<<8, 256>>>();
    scan3<<<dim3(32, 8), 256>>>();
    // per-head C projection + gating
    headmm<<<dim3(MTOK / 64, HH), 256>>>(Cw, Cb);
    // u = z + LN(z), fp16 split
    ln_resid<<<MTOK, 256>>>(gamma, beta);
    // FFN1 + gelu -> mid (fp16 2-prod, fp16 split out)
    gemm_tc<1><<<dim3(16, 32), 256, 3 * 49152>>>(
        uH16, uL16, f1t16, nullptr, ffn1_b,
        nullptr, nullptr, midH16, midL16, 4096, 1024, 2);
    // FFN2 + residual u -> hout (fp16 2-prod)
    gemm_tc<1><<<dim3(16, 8), 256, 3 * 49152>>>(
        midH16, midL16, f2t16, nullptr, ffn2_b,
        uf, nullptr, hoH16, hoL16, 1024, 4096, 0);
    // proj -> p (fp16 2-prod; p hi/lo, out_w consumes hi only)
    gemm_tc<1><<<dim3(16, 8), 256, 3 * 49152>>>(
        hoH16, hoL16, pjt16, nullptr, proj_b,
        nullptr, nullptr, pH16, pL16, 1024, 1024, 0);
    // logits: single-product plain fp16 (dominant GEMM, 2048x32000x1024)
    gemm_tc<2><<<dim3(16, 250), 256, 3 * 32768>>>(
        pH16, nullptr, owt16, nullptr, out_b,
        nullptr, out, nullptr, nullptr, VV, 1024, 0);
}